// round 5
// baseline (speedup 1.0000x reference)
#include <cuda_runtime.h>
#include <math.h>

#define NPTS 40000
#define KNN  16
#define CCH  128
// 1/sqrt(1 + 1e-5)  (BatchNorm eval with running_var = 1)
#define RSQ  0.9999950000374997f

// ---------------- scratch (no allocations allowed) ----------------
static __device__ float g_h  [NPTS * CCH];   // main residual stream
static __device__ float g_xp [NPTS * CCH];   // spse output / lfp proj output
static __device__ float g_tmp[NPTS * 512];   // MLP hidden (max width 512)

__device__ __forceinline__ float gelu_tanh(float x) {
    // jax.nn.gelu(approximate=True)
    float x3 = x * x * x;
    return 0.5f * x * (1.0f + tanhf(0.7978845608028654f * (x + 0.044715f * x3)));
}

// ---------------- spse + BN0 ----------------
__global__ void __launch_bounds__(128) spse_kernel(
    const float* __restrict__ x, const float* __restrict__ xyz,
    const int* __restrict__ knn,
    const float* __restrict__ spse_m, const float* __restrict__ spse_c,
    const float* __restrict__ spse_h,
    const float* __restrict__ g0, const float* __restrict__ b0,
    float* __restrict__ out)
{
    int n = blockIdx.x;
    int c = threadIdx.x;

    float M0x = spse_m[0 * CCH + c], M0y = spse_m[1 * CCH + c], M0z = spse_m[2 * CCH + c];
    float M1x = spse_m[4 * CCH + c], M1y = spse_m[5 * CCH + c], M1z = spse_m[6 * CCH + c];
    float M2x = spse_m[8 * CCH + c], M2y = spse_m[9 * CCH + c], M2z = spse_m[10 * CCH + c];
    float c0 = spse_c[0 * CCH + c]; c0 *= c0;
    float c1 = spse_c[1 * CCH + c]; c1 *= c1;
    float c2 = spse_c[2 * CCH + c]; c2 *= c2;
    float h2 = spse_h[c]; h2 *= h2;

    float px = xyz[n * 3 + 0], py = xyz[n * 3 + 1], pz = xyz[n * 3 + 2];
    float f0 = x[n * 4 + 0], f1 = x[n * 4 + 1], f2 = x[n * 4 + 2], f3 = x[n * 4 + 3];

    float e = 0.0f;
    #pragma unroll
    for (int k = 0; k < KNN; ++k) {
        int nb = knn[n * KNN + k];
        float dx = xyz[nb * 3 + 0] - px;
        float dy = xyz[nb * 3 + 1] - py;
        float dz = xyz[nb * 3 + 2] - pz;
        float r0 = x[nb * 4 + 0] - f0;
        float r1 = x[nb * 4 + 1] - f1;
        float r2 = x[nb * 4 + 2] - f2;
        float r3 = x[nb * 4 + 3] - f3;
        float d0 = dx * M0x + dy * M0y + dz * M0z;
        float d1 = dx * M1x + dy * M1y + dz * M1z;
        float d2 = dx * M2x + dy * M2y + dz * M2z;
        e += d0 * d0 + d1 * d1 + d2 * d2;
        e += r0 * r0 * c0 + r1 * r1 * c1 + r2 * r2 * c2 + r3 * r3 * h2;
    }
    float r = sqrtf(e * (1.0f / (float)KNN));
    out[n * CCH + c] = r * g0[c] * RSQ + b0[c];
}

// ---------------- LFP gather + PE + max + BN + residual ----------------
__global__ void __launch_bounds__(128) lfp_kernel(
    const float* __restrict__ xp, const float* __restrict__ xyz,
    const int* __restrict__ knn,
    const float* __restrict__ coor,  // (3, 32)
    const float* __restrict__ scale, // (32,)
    const float* __restrict__ g, const float* __restrict__ b,
    float* h)
{
    int n = blockIdx.x;
    int c = threadIdx.x;
    int d = c >> 2;
    float s2 = scale[d]; s2 *= s2;
    float k0 = coor[0 * 32 + d] * s2;
    float k1 = coor[1 * 32 + d] * s2;
    float k2 = coor[2 * 32 + d] * s2;

    float px = xyz[n * 3 + 0], py = xyz[n * 3 + 1], pz = xyz[n * 3 + 2];

    float m = -INFINITY;
    #pragma unroll
    for (int k = 0; k < KNN; ++k) {
        int nb = knn[n * KNN + k];
        float pe = (xyz[nb * 3 + 0] - px) * k0
                 + (xyz[nb * 3 + 1] - py) * k1
                 + (xyz[nb * 3 + 2] - pz) * k2;
        float v = xp[nb * CCH + c] + pe;
        m = fmaxf(m, v);
    }
    h[n * CCH + c] = h[n * CCH + c] + (m * g[c] * RSQ + b[c]);
}

// ---------------- TF32 tensor-core GEMM (3xTF32, hi/lo precomputed in smem) ----------------
// C(R x M) = epilogue( prologue(A)(R x K) @ B(K x M) )
// BM=64 rows, BN=128 cols, BK=16, 256 threads (8 warps, 2x4), warp tile 32x32.
// hi/lo tf32 split done ONCE at the global->shared load; mainloop is LDS+HMMA only.
// Tiles live in DYNAMIC shared memory (51200 B > 48 KB static limit).

#define BM 64
#define BN 128
#define BK 16
#define AS_STRIDE 68    // [k][m] layout, bank = (4k+m)%32 all-distinct
#define BS_STRIDE 132   // [k][n] layout, bank = (4k+n)%32 all-distinct

#define A_WORDS (BK * AS_STRIDE)          // per buffer: 1088
#define B_WORDS (BK * BS_STRIDE)          // per buffer: 2112
#define SMEM_WORDS (2 * A_WORDS * 2 + 2 * B_WORDS * 2)   // 12800
#define SMEM_BYTES (SMEM_WORDS * 4)                      // 51200

// indexers into dynamic smem
#define AH(buf,k,m) s_ah[(buf) * A_WORDS + (k) * AS_STRIDE + (m)]
#define AL(buf,k,m) s_al[(buf) * A_WORDS + (k) * AS_STRIDE + (m)]
#define BH(buf,k,n) s_bh[(buf) * B_WORDS + (k) * BS_STRIDE + (n)]
#define BL(buf,k,n) s_bl[(buf) * B_WORDS + (k) * BS_STRIDE + (n)]

__device__ __forceinline__ unsigned f2tf32(float x) {
    unsigned r;
    asm("cvt.rna.tf32.f32 %0, %1;" : "=r"(r) : "f"(x));
    return r;
}

__device__ __forceinline__ void mma884(float* c, const unsigned* a, const unsigned* b) {
    asm volatile(
        "mma.sync.aligned.m16n8k8.row.col.f32.tf32.tf32.f32 "
        "{%0,%1,%2,%3}, {%4,%5,%6,%7}, {%8,%9}, {%0,%1,%2,%3};"
        : "+f"(c[0]), "+f"(c[1]), "+f"(c[2]), "+f"(c[3])
        : "r"(a[0]), "r"(a[1]), "r"(a[2]), "r"(a[3]), "r"(b[0]), "r"(b[1]));
}

__device__ __forceinline__ void split_tf32(float x, unsigned& hi, unsigned& lo) {
    hi = f2tf32(x);
    lo = f2tf32(x - __uint_as_float(hi));
}

__global__ void __launch_bounds__(256) gemm_tc(
    const float* __restrict__ A, const float* __restrict__ B, float* Cout,
    int K, int M,
    const float* __restrict__ a_scale, const float* __restrict__ a_bias,
    const float* __restrict__ bias, int act,
    const float* __restrict__ bn_g, const float* __restrict__ bn_b,
    const float* residual)
{
    extern __shared__ unsigned s_dyn[];
    unsigned* s_ah = s_dyn;
    unsigned* s_al = s_ah + 2 * A_WORDS;
    unsigned* s_bh = s_al + 2 * A_WORDS;
    unsigned* s_bl = s_bh + 2 * B_WORDS;

    int t = threadIdx.x;
    int lane = t & 31, wid = t >> 5;
    int wm = wid >> 2;      // 0..1  -> rows wm*32
    int wn = wid & 3;       // 0..3  -> cols wn*32
    int bm = blockIdx.x * BM;
    int bn = blockIdx.y * BN;
    int gid = lane >> 2;    // groupID 0..7
    int tig = lane & 3;     // thread-in-group 0..3

    // A load mapping: thread -> (row=t/4, k4=(t%4)*4), one float4
    int a_row = t >> 2;
    int a_k4  = (t & 3) << 2;
    // B load mapping: 2 float4 per thread: k=t/32 (+8), n4=(t%32)*4
    int b_k0 = t >> 5;
    int b_n4 = (t & 31) << 2;

    float acc[2][4][4] = {};

    int niter = K / BK;

    // --- preload iter 0 ---
    {
        float4 av = *(const float4*)&A[(size_t)(bm + a_row) * K + a_k4];
        if (a_scale) {
            av.x = av.x * a_scale[a_k4 + 0] * RSQ + a_bias[a_k4 + 0];
            av.y = av.y * a_scale[a_k4 + 1] * RSQ + a_bias[a_k4 + 1];
            av.z = av.z * a_scale[a_k4 + 2] * RSQ + a_bias[a_k4 + 2];
            av.w = av.w * a_scale[a_k4 + 3] * RSQ + a_bias[a_k4 + 3];
        }
        split_tf32(av.x, AH(0, a_k4 + 0, a_row), AL(0, a_k4 + 0, a_row));
        split_tf32(av.y, AH(0, a_k4 + 1, a_row), AL(0, a_k4 + 1, a_row));
        split_tf32(av.z, AH(0, a_k4 + 2, a_row), AL(0, a_k4 + 2, a_row));
        split_tf32(av.w, AH(0, a_k4 + 3, a_row), AL(0, a_k4 + 3, a_row));
        float4 bv0 = *(const float4*)&B[(size_t)(b_k0) * M + bn + b_n4];
        float4 bv1 = *(const float4*)&B[(size_t)(b_k0 + 8) * M + bn + b_n4];
        split_tf32(bv0.x, BH(0, b_k0, b_n4 + 0), BL(0, b_k0, b_n4 + 0));
        split_tf32(bv0.y, BH(0, b_k0, b_n4 + 1), BL(0, b_k0, b_n4 + 1));
        split_tf32(bv0.z, BH(0, b_k0, b_n4 + 2), BL(0, b_k0, b_n4 + 2));
        split_tf32(bv0.w, BH(0, b_k0, b_n4 + 3), BL(0, b_k0, b_n4 + 3));
        split_tf32(bv1.x, BH(0, b_k0 + 8, b_n4 + 0), BL(0, b_k0 + 8, b_n4 + 0));
        split_tf32(bv1.y, BH(0, b_k0 + 8, b_n4 + 1), BL(0, b_k0 + 8, b_n4 + 1));
        split_tf32(bv1.z, BH(0, b_k0 + 8, b_n4 + 2), BL(0, b_k0 + 8, b_n4 + 2));
        split_tf32(bv1.w, BH(0, b_k0 + 8, b_n4 + 3), BL(0, b_k0 + 8, b_n4 + 3));
    }
    __syncthreads();

    for (int it = 0; it < niter; ++it) {
        int cur = it & 1;
        float4 av, bv0, bv1;
        if (it + 1 < niter) {
            int k0 = (it + 1) * BK;
            av = *(const float4*)&A[(size_t)(bm + a_row) * K + k0 + a_k4];
            if (a_scale) {
                av.x = av.x * a_scale[k0 + a_k4 + 0] * RSQ + a_bias[k0 + a_k4 + 0];
                av.y = av.y * a_scale[k0 + a_k4 + 1] * RSQ + a_bias[k0 + a_k4 + 1];
                av.z = av.z * a_scale[k0 + a_k4 + 2] * RSQ + a_bias[k0 + a_k4 + 2];
                av.w = av.w * a_scale[k0 + a_k4 + 3] * RSQ + a_bias[k0 + a_k4 + 3];
            }
            bv0 = *(const float4*)&B[(size_t)(k0 + b_k0) * M + bn + b_n4];
            bv1 = *(const float4*)&B[(size_t)(k0 + b_k0 + 8) * M + bn + b_n4];
        }

        // compute on smem[cur]: pure LDS + HMMA
        #pragma unroll
        for (int ks = 0; ks < BK; ks += 8) {
            unsigned ah[2][4], al[2][4], bh[4][2], bl[4][2];
            #pragma unroll
            for (int mt = 0; mt < 2; ++mt) {
                int m0 = wm * 32 + mt * 16 + gid;
                ah[mt][0] = AH(cur, ks + tig    , m0);
                ah[mt][1] = AH(cur, ks + tig    , m0 + 8);
                ah[mt][2] = AH(cur, ks + tig + 4, m0);
                ah[mt][3] = AH(cur, ks + tig + 4, m0 + 8);
                al[mt][0] = AL(cur, ks + tig    , m0);
                al[mt][1] = AL(cur, ks + tig    , m0 + 8);
                al[mt][2] = AL(cur, ks + tig + 4, m0);
                al[mt][3] = AL(cur, ks + tig + 4, m0 + 8);
            }
            #pragma unroll
            for (int nt = 0; nt < 4; ++nt) {
                int n0 = wn * 32 + nt * 8 + gid;
                bh[nt][0] = BH(cur, ks + tig    , n0);
                bh[nt][1] = BH(cur, ks + tig + 4, n0);
                bl[nt][0] = BL(cur, ks + tig    , n0);
                bl[nt][1] = BL(cur, ks + tig + 4, n0);
            }
            #pragma unroll
            for (int mt = 0; mt < 2; ++mt)
                #pragma unroll
                for (int nt = 0; nt < 4; ++nt) {
                    mma884(acc[mt][nt], al[mt], bh[nt]);
                    mma884(acc[mt][nt], ah[mt], bl[nt]);
                    mma884(acc[mt][nt], ah[mt], bh[nt]);
                }
        }

        if (it + 1 < niter) {
            int nxt = cur ^ 1;
            split_tf32(av.x, AH(nxt, a_k4 + 0, a_row), AL(nxt, a_k4 + 0, a_row));
            split_tf32(av.y, AH(nxt, a_k4 + 1, a_row), AL(nxt, a_k4 + 1, a_row));
            split_tf32(av.z, AH(nxt, a_k4 + 2, a_row), AL(nxt, a_k4 + 2, a_row));
            split_tf32(av.w, AH(nxt, a_k4 + 3, a_row), AL(nxt, a_k4 + 3, a_row));
            split_tf32(bv0.x, BH(nxt, b_k0, b_n4 + 0), BL(nxt, b_k0, b_n4 + 0));
            split_tf32(bv0.y, BH(nxt, b_k0, b_n4 + 1), BL(nxt, b_k0, b_n4 + 1));
            split_tf32(bv0.z, BH(nxt, b_k0, b_n4 + 2), BL(nxt, b_k0, b_n4 + 2));
            split_tf32(bv0.w, BH(nxt, b_k0, b_n4 + 3), BL(nxt, b_k0, b_n4 + 3));
            split_tf32(bv1.x, BH(nxt, b_k0 + 8, b_n4 + 0), BL(nxt, b_k0 + 8, b_n4 + 0));
            split_tf32(bv1.y, BH(nxt, b_k0 + 8, b_n4 + 1), BL(nxt, b_k0 + 8, b_n4 + 1));
            split_tf32(bv1.z, BH(nxt, b_k0 + 8, b_n4 + 2), BL(nxt, b_k0 + 8, b_n4 + 2));
            split_tf32(bv1.w, BH(nxt, b_k0 + 8, b_n4 + 3), BL(nxt, b_k0 + 8, b_n4 + 3));
            __syncthreads();
        }
    }

    // --- epilogue ---
    #pragma unroll
    for (int mt = 0; mt < 2; ++mt) {
        #pragma unroll
        for (int nt = 0; nt < 4; ++nt) {
            int c0 = bn + wn * 32 + nt * 8 + tig * 2;
            #pragma unroll
            for (int half = 0; half < 2; ++half) {
                int row = bm + wm * 32 + mt * 16 + gid + half * 8;
                float v0 = acc[mt][nt][half * 2 + 0];
                float v1 = acc[mt][nt][half * 2 + 1];
                if (bias) { v0 += bias[c0]; v1 += bias[c0 + 1]; }
                if (act)  { v0 = gelu_tanh(v0); v1 = gelu_tanh(v1); }
                if (bn_g) {
                    v0 = v0 * bn_g[c0] * RSQ + bn_b[c0];
                    v1 = v1 * bn_g[c0 + 1] * RSQ + bn_b[c0 + 1];
                }
                size_t idx = (size_t)row * M + c0;
                if (residual) { v0 += residual[idx]; v1 += residual[idx + 1]; }
                *(float2*)&Cout[idx] = make_float2(v0, v1);
            }
        }
    }
}

// ---------------- driver ----------------
extern "C" void kernel_launch(void* const* d_in, const int* in_sizes, int n_in,
                              void* d_out, int out_size)
{
    const float* x      = (const float*)d_in[0];
    const float* xyz    = (const float*)d_in[1];
    const int*   knn    = (const int*)  d_in[2];
    const float* spse_m = (const float*)d_in[3];
    const float* spse_c = (const float*)d_in[4];
    const float* spse_h = (const float*)d_in[5];
    const float* bn0g   = (const float*)d_in[6];
    const float* bn0b   = (const float*)d_in[7];
    const float* w1     = (const float*)d_in[8];
    const float* b1     = (const float*)d_in[9];
    const float* w2     = (const float*)d_in[10];
    const float* bng    = (const float*)d_in[11];
    const float* bnb    = (const float*)d_in[12];
    const float* proj   = (const float*)d_in[13];
    const float* coor   = (const float*)d_in[14];
    const float* scl    = (const float*)d_in[15];
    const float* lbng   = (const float*)d_in[16];
    const float* lbnb   = (const float*)d_in[17];
    const float* mw1    = (const float*)d_in[18];
    const float* mb1    = (const float*)d_in[19];
    const float* mw2    = (const float*)d_in[20];
    const float* mbng   = (const float*)d_in[21];
    const float* mbnb   = (const float*)d_in[22];
    const float* pg     = (const float*)d_in[23];
    const float* pb     = (const float*)d_in[24];
    const float* pw     = (const float*)d_in[25];
    float* out = (float*)d_out;

    float *h, *xp, *tmp;
    cudaGetSymbolAddress((void**)&h,   g_h);
    cudaGetSymbolAddress((void**)&xp,  g_xp);
    cudaGetSymbolAddress((void**)&tmp, g_tmp);

    // opt into >48KB dynamic smem (host-side attribute, no allocation, capture-safe)
    static bool smem_set = false;
    if (!smem_set) {
        cudaFuncSetAttribute(gemm_tc, cudaFuncAttributeMaxDynamicSharedMemorySize,
                             SMEM_BYTES);
        smem_set = true;
    }

    dim3 blk(256);
    dim3 gM128(625, 1), gM256(625, 2), gM512(625, 4);
    const int SB = SMEM_BYTES;

    // nbr = bn0(knn_spse4(...))
    spse_kernel<<<NPTS, 128>>>(x, xyz, knn, spse_m, spse_c, spse_h, bn0g, bn0b, xp);
    // h = bn( gelu(nbr @ w1 + b1) @ w2 )
    gemm_tc<<<gM256, blk, SB>>>(xp, w1, tmp, 128, 256, 0, 0, b1, 1, 0, 0, 0);
    gemm_tc<<<gM128, blk, SB>>>(tmp, w2, h, 256, 128, 0, 0, 0, 0, bng, bnb, 0);
    // h += mlp0(h)
    gemm_tc<<<gM512, blk, SB>>>(h, mw1, tmp, 128, 512, 0, 0, mb1, 1, 0, 0, 0);
    gemm_tc<<<gM128, blk, SB>>>(tmp, mw2, h, 512, 128, 0, 0, 0, 0, mbng, mbnb, h);

    for (int i = 0; i < 4; ++i) {
        gemm_tc<<<gM128, blk, SB>>>(h, proj + (size_t)i * CCH * CCH, xp, 128, 128,
                                    0, 0, 0, 0, 0, 0, 0);
        lfp_kernel<<<NPTS, 128>>>(xp, xyz, knn, coor + i * 3 * 32, scl + i * 32,
                                  lbng + i * CCH, lbnb + i * CCH, h);
        if (i & 1) {
            int j = i / 2 + 1;
            gemm_tc<<<gM512, blk, SB>>>(h, mw1 + (size_t)j * CCH * 512, tmp, 128, 512,
                                        0, 0, mb1 + j * 512, 1, 0, 0, 0);
            gemm_tc<<<gM128, blk, SB>>>(tmp, mw2 + (size_t)j * 512 * CCH, h, 512, 128,
                                        0, 0, 0, 0, mbng + j * CCH, mbnb + j * CCH, h);
        }
    }
    // out = bn(h) @ post_w   (BN folded into A prologue)
    gemm_tc<<<gM256, blk, SB>>>(h, pw, out, 128, 256, pg, pb, 0, 0, 0, 0, 0);
}

// round 6
// speedup vs baseline: 1.4929x; 1.4929x over previous
#include <cuda_runtime.h>
#include <cuda_fp16.h>
#include <math.h>

#define NPTS 40000
#define KNN  16
#define CCH  128
// 1/sqrt(1 + 1e-5)  (BatchNorm eval with running_var = 1)
#define RSQ  0.9999950000374997f

// ---------------- scratch (no allocations allowed) ----------------
static __device__ float g_h  [NPTS * CCH];   // main residual stream
static __device__ float g_xp [NPTS * CCH];   // spse output / lfp proj output
static __device__ float g_tmp[NPTS * 512];   // MLP hidden (max width 512)

__device__ __forceinline__ float gelu_tanh(float x) {
    // jax.nn.gelu(approximate=True)
    float x3 = x * x * x;
    return 0.5f * x * (1.0f + tanhf(0.7978845608028654f * (x + 0.044715f * x3)));
}

// ---------------- spse + BN0 ----------------
__global__ void __launch_bounds__(128) spse_kernel(
    const float* __restrict__ x, const float* __restrict__ xyz,
    const int* __restrict__ knn,
    const float* __restrict__ spse_m, const float* __restrict__ spse_c,
    const float* __restrict__ spse_h,
    const float* __restrict__ g0, const float* __restrict__ b0,
    float* __restrict__ out)
{
    int n = blockIdx.x;
    int c = threadIdx.x;

    float M0x = spse_m[0 * CCH + c], M0y = spse_m[1 * CCH + c], M0z = spse_m[2 * CCH + c];
    float M1x = spse_m[4 * CCH + c], M1y = spse_m[5 * CCH + c], M1z = spse_m[6 * CCH + c];
    float M2x = spse_m[8 * CCH + c], M2y = spse_m[9 * CCH + c], M2z = spse_m[10 * CCH + c];
    float c0 = spse_c[0 * CCH + c]; c0 *= c0;
    float c1 = spse_c[1 * CCH + c]; c1 *= c1;
    float c2 = spse_c[2 * CCH + c]; c2 *= c2;
    float h2 = spse_h[c]; h2 *= h2;

    float px = xyz[n * 3 + 0], py = xyz[n * 3 + 1], pz = xyz[n * 3 + 2];
    float f0 = x[n * 4 + 0], f1 = x[n * 4 + 1], f2 = x[n * 4 + 2], f3 = x[n * 4 + 3];

    float e = 0.0f;
    #pragma unroll
    for (int k = 0; k < KNN; ++k) {
        int nb = knn[n * KNN + k];
        float dx = xyz[nb * 3 + 0] - px;
        float dy = xyz[nb * 3 + 1] - py;
        float dz = xyz[nb * 3 + 2] - pz;
        float r0 = x[nb * 4 + 0] - f0;
        float r1 = x[nb * 4 + 1] - f1;
        float r2 = x[nb * 4 + 2] - f2;
        float r3 = x[nb * 4 + 3] - f3;
        float d0 = dx * M0x + dy * M0y + dz * M0z;
        float d1 = dx * M1x + dy * M1y + dz * M1z;
        float d2 = dx * M2x + dy * M2y + dz * M2z;
        e += d0 * d0 + d1 * d1 + d2 * d2;
        e += r0 * r0 * c0 + r1 * r1 * c1 + r2 * r2 * c2 + r3 * r3 * h2;
    }
    float r = sqrtf(e * (1.0f / (float)KNN));
    out[n * CCH + c] = r * g0[c] * RSQ + b0[c];
}

// ---------------- LFP gather + PE + max + BN + residual ----------------
__global__ void __launch_bounds__(128) lfp_kernel(
    const float* __restrict__ xp, const float* __restrict__ xyz,
    const int* __restrict__ knn,
    const float* __restrict__ coor,  // (3, 32)
    const float* __restrict__ scale, // (32,)
    const float* __restrict__ g, const float* __restrict__ b,
    float* h)
{
    int n = blockIdx.x;
    int c = threadIdx.x;
    int d = c >> 2;
    float s2 = scale[d]; s2 *= s2;
    float k0 = coor[0 * 32 + d] * s2;
    float k1 = coor[1 * 32 + d] * s2;
    float k2 = coor[2 * 32 + d] * s2;

    float px = xyz[n * 3 + 0], py = xyz[n * 3 + 1], pz = xyz[n * 3 + 2];

    float m = -INFINITY;
    #pragma unroll
    for (int k = 0; k < KNN; ++k) {
        int nb = knn[n * KNN + k];
        float pe = (xyz[nb * 3 + 0] - px) * k0
                 + (xyz[nb * 3 + 1] - py) * k1
                 + (xyz[nb * 3 + 2] - pz) * k2;
        float v = xp[nb * CCH + c] + pe;
        m = fmaxf(m, v);
    }
    h[n * CCH + c] = h[n * CCH + c] + (m * g[c] * RSQ + b[c]);
}

// ---------------- split-fp16 tensor-core GEMM (3-term, ldmatrix) ----------------
// C(R x M) = epilogue( prologue(A)(R x K) @ B(K x M) )
// BM=64, BN=128, BK=16, 256 threads (8 warps, 2x4), warp tile 32x32.
// fp16 hi/lo split at global->shared load; smem as two khalf planes of 16B rows;
// fragments via ldmatrix.x4 (conflict-free); mma.m16n8k16.f32.f16.f16.f32 x3 terms.

#define BM 64
#define BN 128
#define BK 16

// smem: [buf][khalf][row][8] fp16. 16B rows -> conflict-free LDSM phases.
#define A_BUF_HALF (2 * BM * 8)    // elems per buffer: 1024  (2048 B)
#define B_BUF_HALF (2 * BN * 8)    // elems per buffer: 2048  (4096 B)

__device__ __forceinline__ unsigned su32(const void* p) {
    return (unsigned)__cvta_generic_to_shared(p);
}

__device__ __forceinline__ void ldsm4(unsigned& r0, unsigned& r1, unsigned& r2,
                                      unsigned& r3, unsigned addr) {
    asm volatile("ldmatrix.sync.aligned.m8n8.x4.shared.b16 {%0,%1,%2,%3}, [%4];"
                 : "=r"(r0), "=r"(r1), "=r"(r2), "=r"(r3) : "r"(addr));
}

__device__ __forceinline__ void mma16(float* c, const unsigned* a, const unsigned* b) {
    asm volatile(
        "mma.sync.aligned.m16n8k16.row.col.f32.f16.f16.f32 "
        "{%0,%1,%2,%3}, {%4,%5,%6,%7}, {%8,%9}, {%0,%1,%2,%3};"
        : "+f"(c[0]), "+f"(c[1]), "+f"(c[2]), "+f"(c[3])
        : "r"(a[0]), "r"(a[1]), "r"(a[2]), "r"(a[3]), "r"(b[0]), "r"(b[1]));
}

// split a,b into fp16 hi pair + fp16 lo pair (a in low half)
__device__ __forceinline__ void split2h(float a, float b, unsigned& hi, unsigned& lo) {
    __half ha = __float2half_rn(a);
    __half hb = __float2half_rn(b);
    __half la = __float2half_rn(a - __half2float(ha));
    __half lb = __float2half_rn(b - __half2float(hb));
    __half2 H = __halves2half2(ha, hb);
    __half2 L = __halves2half2(la, lb);
    hi = *reinterpret_cast<unsigned*>(&H);
    lo = *reinterpret_cast<unsigned*>(&L);
}

__global__ void __launch_bounds__(256) gemm_tc(
    const float* __restrict__ A, const float* __restrict__ B, float* Cout,
    int K, int M,
    const float* __restrict__ a_scale, const float* __restrict__ a_bias,
    const float* __restrict__ bias, int act,
    const float* __restrict__ bn_g, const float* __restrict__ bn_b,
    const float* residual)
{
    __shared__ __align__(16) __half sAh[2][2][BM][8];
    __shared__ __align__(16) __half sAl[2][2][BM][8];
    __shared__ __align__(16) __half sBh[2][2][BN][8];
    __shared__ __align__(16) __half sBl[2][2][BN][8];

    int t = threadIdx.x;
    int lane = t & 31, wid = t >> 5;
    int wm = wid >> 2;      // 0..1  -> rows wm*32
    int wn = wid & 3;       // 0..3  -> cols wn*32
    int bm = blockIdx.x * BM;
    int bn = blockIdx.y * BN;
    int gid = lane >> 2;    // groupID 0..7
    int tig = lane & 3;     // thread-in-group 0..3

    // ---- ldmatrix per-lane addresses (loop-invariant; +buf offset in loop) ----
    // A .x4 matrices: (m0..7,kh0),(m8..15,kh0),(m0..7,kh1),(m8..15,kh1)
    int a_lm  = (lane & 7) + ((lane >> 3) & 1) * 8;
    int a_lkh = (lane >> 4) & 1;
    unsigned aAdH[2], aAdL[2];
    #pragma unroll
    for (int mt = 0; mt < 2; ++mt) {
        int m = wm * 32 + mt * 16 + a_lm;
        aAdH[mt] = su32(&sAh[0][a_lkh][m][0]);
        aAdL[mt] = su32(&sAl[0][a_lkh][m][0]);
    }
    // B .x4 matrices: (n0..7,kh0),(n0..7,kh1),(n8..15,kh0),(n8..15,kh1)
    int b_ln  = (lane & 7) + ((lane >> 4) & 1) * 8;
    int b_lkh = (lane >> 3) & 1;
    unsigned bAdH[2], bAdL[2];
    #pragma unroll
    for (int ntp = 0; ntp < 2; ++ntp) {
        int n = wn * 32 + ntp * 16 + b_ln;
        bAdH[ntp] = su32(&sBh[0][b_lkh][n][0]);
        bAdL[ntp] = su32(&sBl[0][b_lkh][n][0]);
    }
    const unsigned ABUF = A_BUF_HALF * 2;   // bytes per A buffer (2048)
    const unsigned BBUF = B_BUF_HALF * 2;   // bytes per B buffer (4096)

    // ---- global load mappings ----
    // A: thread -> (row=t/4, k4=(t%4)*4), one float4
    int a_row = t >> 2;
    int a_k4  = (t & 3) << 2;
    int a_kh  = a_k4 >> 3;
    int a_kc  = a_k4 & 7;
    // B: thread -> (n=t&127, kh=t>>7); loads 8 k values (rows), coalesced in n
    int b_n  = t & 127;
    int b_kh = t >> 7;

    float acc[2][4][4] = {};
    int niter = K / BK;

    // ---- preload buffer 0 ----
    {
        float4 av = *(const float4*)&A[(size_t)(bm + a_row) * K + a_k4];
        if (a_scale) {
            av.x = av.x * a_scale[a_k4 + 0] * RSQ + a_bias[a_k4 + 0];
            av.y = av.y * a_scale[a_k4 + 1] * RSQ + a_bias[a_k4 + 1];
            av.z = av.z * a_scale[a_k4 + 2] * RSQ + a_bias[a_k4 + 2];
            av.w = av.w * a_scale[a_k4 + 3] * RSQ + a_bias[a_k4 + 3];
        }
        unsigned h0, l0, h1, l1;
        split2h(av.x, av.y, h0, l0);
        split2h(av.z, av.w, h1, l1);
        *(uint2*)&sAh[0][a_kh][a_row][a_kc] = make_uint2(h0, h1);
        *(uint2*)&sAl[0][a_kh][a_row][a_kc] = make_uint2(l0, l1);

        float f[8];
        #pragma unroll
        for (int j = 0; j < 8; ++j)
            f[j] = B[(size_t)(b_kh * 8 + j) * M + bn + b_n];
        unsigned bh4[4], bl4[4];
        #pragma unroll
        for (int p = 0; p < 4; ++p)
            split2h(f[2 * p], f[2 * p + 1], bh4[p], bl4[p]);
        *(uint4*)&sBh[0][b_kh][b_n][0] = make_uint4(bh4[0], bh4[1], bh4[2], bh4[3]);
        *(uint4*)&sBl[0][b_kh][b_n][0] = make_uint4(bl4[0], bl4[1], bl4[2], bl4[3]);
    }
    __syncthreads();

    for (int it = 0; it < niter; ++it) {
        int cur = it & 1;
        bool more = (it + 1 < niter);

        // prefetch next tile into registers
        float4 av; float f[8];
        if (more) {
            int k0 = (it + 1) * BK;
            av = *(const float4*)&A[(size_t)(bm + a_row) * K + k0 + a_k4];
            if (a_scale) {
                av.x = av.x * a_scale[k0 + a_k4 + 0] * RSQ + a_bias[k0 + a_k4 + 0];
                av.y = av.y * a_scale[k0 + a_k4 + 1] * RSQ + a_bias[k0 + a_k4 + 1];
                av.z = av.z * a_scale[k0 + a_k4 + 2] * RSQ + a_bias[k0 + a_k4 + 2];
                av.w = av.w * a_scale[k0 + a_k4 + 3] * RSQ + a_bias[k0 + a_k4 + 3];
            }
            #pragma unroll
            for (int j = 0; j < 8; ++j)
                f[j] = B[(size_t)(k0 + b_kh * 8 + j) * M + bn + b_n];
        }

        // fragments via ldmatrix
        unsigned ah[2][4], al[2][4], bh[4][2], bl[4][2];
        #pragma unroll
        for (int mt = 0; mt < 2; ++mt) {
            ldsm4(ah[mt][0], ah[mt][1], ah[mt][2], ah[mt][3], aAdH[mt] + cur * ABUF);
            ldsm4(al[mt][0], al[mt][1], al[mt][2], al[mt][3], aAdL[mt] + cur * ABUF);
        }
        #pragma unroll
        for (int ntp = 0; ntp < 2; ++ntp) {
            unsigned r0, r1, r2, r3;
            ldsm4(r0, r1, r2, r3, bAdH[ntp] + cur * BBUF);
            bh[ntp * 2][0] = r0; bh[ntp * 2][1] = r1;
            bh[ntp * 2 + 1][0] = r2; bh[ntp * 2 + 1][1] = r3;
            ldsm4(r0, r1, r2, r3, bAdL[ntp] + cur * BBUF);
            bl[ntp * 2][0] = r0; bl[ntp * 2][1] = r1;
            bl[ntp * 2 + 1][0] = r2; bl[ntp * 2 + 1][1] = r3;
        }

        #pragma unroll
        for (int mt = 0; mt < 2; ++mt)
            #pragma unroll
            for (int nt = 0; nt < 4; ++nt) {
                mma16(acc[mt][nt], al[mt], bh[nt]);
                mma16(acc[mt][nt], ah[mt], bl[nt]);
                mma16(acc[mt][nt], ah[mt], bh[nt]);
            }

        if (more) {
            int nxt = cur ^ 1;
            unsigned h0, l0, h1, l1;
            split2h(av.x, av.y, h0, l0);
            split2h(av.z, av.w, h1, l1);
            *(uint2*)&sAh[nxt][a_kh][a_row][a_kc] = make_uint2(h0, h1);
            *(uint2*)&sAl[nxt][a_kh][a_row][a_kc] = make_uint2(l0, l1);
            unsigned bh4[4], bl4[4];
            #pragma unroll
            for (int p = 0; p < 4; ++p)
                split2h(f[2 * p], f[2 * p + 1], bh4[p], bl4[p]);
            *(uint4*)&sBh[nxt][b_kh][b_n][0] = make_uint4(bh4[0], bh4[1], bh4[2], bh4[3]);
            *(uint4*)&sBl[nxt][b_kh][b_n][0] = make_uint4(bl4[0], bl4[1], bl4[2], bl4[3]);
            __syncthreads();
        }
    }

    // --- epilogue (mma C layout: c0,c1 -> row gid, cols tig*2,+1; c2,c3 -> row gid+8) ---
    #pragma unroll
    for (int mt = 0; mt < 2; ++mt) {
        #pragma unroll
        for (int nt = 0; nt < 4; ++nt) {
            int c0 = bn + wn * 32 + nt * 8 + tig * 2;
            #pragma unroll
            for (int half = 0; half < 2; ++half) {
                int row = bm + wm * 32 + mt * 16 + gid + half * 8;
                float v0 = acc[mt][nt][half * 2 + 0];
                float v1 = acc[mt][nt][half * 2 + 1];
                if (bias) { v0 += bias[c0]; v1 += bias[c0 + 1]; }
                if (act)  { v0 = gelu_tanh(v0); v1 = gelu_tanh(v1); }
                if (bn_g) {
                    v0 = v0 * bn_g[c0] * RSQ + bn_b[c0];
                    v1 = v1 * bn_g[c0 + 1] * RSQ + bn_b[c0 + 1];
                }
                size_t idx = (size_t)row * M + c0;
                if (residual) { v0 += residual[idx]; v1 += residual[idx + 1]; }
                *(float2*)&Cout[idx] = make_float2(v0, v1);
            }
        }
    }
}

// ---------------- driver ----------------
extern "C" void kernel_launch(void* const* d_in, const int* in_sizes, int n_in,
                              void* d_out, int out_size)
{
    const float* x      = (const float*)d_in[0];
    const float* xyz    = (const float*)d_in[1];
    const int*   knn    = (const int*)  d_in[2];
    const float* spse_m = (const float*)d_in[3];
    const float* spse_c = (const float*)d_in[4];
    const float* spse_h = (const float*)d_in[5];
    const float* bn0g   = (const float*)d_in[6];
    const float* bn0b   = (const float*)d_in[7];
    const float* w1     = (const float*)d_in[8];
    const float* b1     = (const float*)d_in[9];
    const float* w2     = (const float*)d_in[10];
    const float* bng    = (const float*)d_in[11];
    const float* bnb    = (const float*)d_in[12];
    const float* proj   = (const float*)d_in[13];
    const float* coor   = (const float*)d_in[14];
    const float* scl    = (const float*)d_in[15];
    const float* lbng   = (const float*)d_in[16];
    const float* lbnb   = (const float*)d_in[17];
    const float* mw1    = (const float*)d_in[18];
    const float* mb1    = (const float*)d_in[19];
    const float* mw2    = (const float*)d_in[20];
    const float* mbng   = (const float*)d_in[21];
    const float* mbnb   = (const float*)d_in[22];
    const float* pg     = (const float*)d_in[23];
    const float* pb     = (const float*)d_in[24];
    const float* pw     = (const float*)d_in[25];
    float* out = (float*)d_out;

    float *h, *xp, *tmp;
    cudaGetSymbolAddress((void**)&h,   g_h);
    cudaGetSymbolAddress((void**)&xp,  g_xp);
    cudaGetSymbolAddress((void**)&tmp, g_tmp);

    dim3 blk(256);
    dim3 gM128(625, 1), gM256(625, 2), gM512(625, 4);

    // nbr = bn0(knn_spse4(...))
    spse_kernel<<<NPTS, 128>>>(x, xyz, knn, spse_m, spse_c, spse_h, bn0g, bn0b, xp);
    // h = bn( gelu(nbr @ w1 + b1) @ w2 )
    gemm_tc<<<gM256, blk>>>(xp, w1, tmp, 128, 256, 0, 0, b1, 1, 0, 0, 0);
    gemm_tc<<<gM128, blk>>>(tmp, w2, h, 256, 128, 0, 0, 0, 0, bng, bnb, 0);
    // h += mlp0(h)
    gemm_tc<<<gM512, blk>>>(h, mw1, tmp, 128, 512, 0, 0, mb1, 1, 0, 0, 0);
    gemm_tc<<<gM128, blk>>>(tmp, mw2, h, 512, 128, 0, 0, 0, 0, mbng, mbnb, h);

    for (int i = 0; i < 4; ++i) {
        gemm_tc<<<gM128, blk>>>(h, proj + (size_t)i * CCH * CCH, xp, 128, 128,
                                0, 0, 0, 0, 0, 0, 0);
        lfp_kernel<<<NPTS, 128>>>(xp, xyz, knn, coor + i * 3 * 32, scl + i * 32,
                                  lbng + i * CCH, lbnb + i * CCH, h);
        if (i & 1) {
            int j = i / 2 + 1;
            gemm_tc<<<gM512, blk>>>(h, mw1 + (size_t)j * CCH * 512, tmp, 128, 512,
                                    0, 0, mb1 + j * 512, 1, 0, 0, 0);
            gemm_tc<<<gM128, blk>>>(tmp, mw2 + (size_t)j * 512 * CCH, h, 512, 128,
                                    0, 0, 0, 0, mbng + j * CCH, mbnb + j * CCH, h);
        }
    }
    // out = bn(h) @ post_w   (BN folded into A prologue)
    gemm_tc<<<gM256, blk>>>(h, pw, out, 128, 256, pg, pb, 0, 0, 0, 0, 0);
}

// round 7
// speedup vs baseline: 1.5151x; 1.0149x over previous
#include <cuda_runtime.h>
#include <cuda_fp16.h>
#include <math.h>

#define NPTS 40000
#define KNN  16
#define CCH  128
// 1/sqrt(1 + 1e-5)  (BatchNorm eval with running_var = 1)
#define RSQ  0.9999950000374997f

// ---------------- scratch (no allocations allowed) ----------------
static __device__ float g_h  [NPTS * CCH];   // main residual stream
static __device__ float g_xp [NPTS * CCH];   // spse output / lfp proj output
static __device__ float g_tmp[NPTS * 512];   // MLP hidden (max width 512)

// pre-split weights (fp16 hi/lo), pre-tiled as [kt][khalf][n][8]
#define OFF_W1   0         // (128,256)
#define OFF_W2   32768     // (256,128)
#define OFF_MW1  65536     // 3 x (128,512)
#define OFF_MW2  262144    // 3 x (512,128)
#define OFF_PROJ 458752    // 4 x (128,128)
#define OFF_PW   524288    // (128,256)
#define WTOT     557056
static __device__ __half g_whi[WTOT];
static __device__ __half g_wlo[WTOT];

__device__ __forceinline__ float gelu_tanh(float x) {
    // jax.nn.gelu(approximate=True)
    float x3 = x * x * x;
    return 0.5f * x * (1.0f + tanhf(0.7978845608028654f * (x + 0.044715f * x3)));
}

// ---------------- weight pre-split: f32 -> fp16 hi/lo, tiled [kt][kh][n][8] ----------------
__device__ __forceinline__ void wsplit_one(const float* __restrict__ W, int lidx,
                                           int M, int base) {
    int k = lidx / M, n = lidx - k * M;
    int kt = k >> 4, kh = (k >> 3) & 1, j = k & 7;
    float v = W[lidx];
    __half h = __float2half_rn(v);
    int dst = base + (((kt * 2 + kh) * M + n) << 3) + j;
    g_whi[dst] = h;
    g_wlo[dst] = __float2half_rn(v - __half2float(h));
}

__global__ void __launch_bounds__(256) wsplit_all(
    const float* __restrict__ w1, const float* __restrict__ w2,
    const float* __restrict__ mw1, const float* __restrict__ mw2,
    const float* __restrict__ proj, const float* __restrict__ pw)
{
    int idx = blockIdx.x * 256 + threadIdx.x;
    if (idx < 32768) wsplit_one(w1, idx, 256, OFF_W1);
    else if (idx < 65536) wsplit_one(w2, idx - 32768, 128, OFF_W2);
    else if (idx < 262144) {
        int l = idx - 65536; int j = l >> 16;
        wsplit_one(mw1 + (j << 16), l & 65535, 512, OFF_MW1 + (j << 16));
    } else if (idx < 458752) {
        int l = idx - 262144; int j = l >> 16;
        wsplit_one(mw2 + (j << 16), l & 65535, 128, OFF_MW2 + (j << 16));
    } else if (idx < 524288) {
        int l = idx - 458752; int i = l >> 14;
        wsplit_one(proj + (i << 14), l & 16383, 128, OFF_PROJ + (i << 14));
    } else if (idx < WTOT) wsplit_one(pw, idx - 524288, 256, OFF_PW);
}

// ---------------- spse + BN0 ----------------
__global__ void __launch_bounds__(128) spse_kernel(
    const float* __restrict__ x, const float* __restrict__ xyz,
    const int* __restrict__ knn,
    const float* __restrict__ spse_m, const float* __restrict__ spse_c,
    const float* __restrict__ spse_h,
    const float* __restrict__ g0, const float* __restrict__ b0,
    float* __restrict__ out)
{
    int n = blockIdx.x;
    int c = threadIdx.x;

    float M0x = spse_m[0 * CCH + c], M0y = spse_m[1 * CCH + c], M0z = spse_m[2 * CCH + c];
    float M1x = spse_m[4 * CCH + c], M1y = spse_m[5 * CCH + c], M1z = spse_m[6 * CCH + c];
    float M2x = spse_m[8 * CCH + c], M2y = spse_m[9 * CCH + c], M2z = spse_m[10 * CCH + c];
    float c0 = spse_c[0 * CCH + c]; c0 *= c0;
    float c1 = spse_c[1 * CCH + c]; c1 *= c1;
    float c2 = spse_c[2 * CCH + c]; c2 *= c2;
    float h2 = spse_h[c]; h2 *= h2;

    float px = xyz[n * 3 + 0], py = xyz[n * 3 + 1], pz = xyz[n * 3 + 2];
    float f0 = x[n * 4 + 0], f1 = x[n * 4 + 1], f2 = x[n * 4 + 2], f3 = x[n * 4 + 3];

    float e = 0.0f;
    #pragma unroll
    for (int k = 0; k < KNN; ++k) {
        int nb = knn[n * KNN + k];
        float dx = xyz[nb * 3 + 0] - px;
        float dy = xyz[nb * 3 + 1] - py;
        float dz = xyz[nb * 3 + 2] - pz;
        float r0 = x[nb * 4 + 0] - f0;
        float r1 = x[nb * 4 + 1] - f1;
        float r2 = x[nb * 4 + 2] - f2;
        float r3 = x[nb * 4 + 3] - f3;
        float d0 = dx * M0x + dy * M0y + dz * M0z;
        float d1 = dx * M1x + dy * M1y + dz * M1z;
        float d2 = dx * M2x + dy * M2y + dz * M2z;
        e += d0 * d0 + d1 * d1 + d2 * d2;
        e += r0 * r0 * c0 + r1 * r1 * c1 + r2 * r2 * c2 + r3 * r3 * h2;
    }
    float r = sqrtf(e * (1.0f / (float)KNN));
    out[n * CCH + c] = r * g0[c] * RSQ + b0[c];
}

// ---------------- LFP gather + PE + max + BN + residual ----------------
__global__ void __launch_bounds__(128) lfp_kernel(
    const float* __restrict__ xp, const float* __restrict__ xyz,
    const int* __restrict__ knn,
    const float* __restrict__ coor,  // (3, 32)
    const float* __restrict__ scale, // (32,)
    const float* __restrict__ g, const float* __restrict__ b,
    float* h)
{
    int n = blockIdx.x;
    int c = threadIdx.x;
    int d = c >> 2;
    float s2 = scale[d]; s2 *= s2;
    float k0 = coor[0 * 32 + d] * s2;
    float k1 = coor[1 * 32 + d] * s2;
    float k2 = coor[2 * 32 + d] * s2;

    float px = xyz[n * 3 + 0], py = xyz[n * 3 + 1], pz = xyz[n * 3 + 2];

    float m = -INFINITY;
    #pragma unroll
    for (int k = 0; k < KNN; ++k) {
        int nb = knn[n * KNN + k];
        float pe = (xyz[nb * 3 + 0] - px) * k0
                 + (xyz[nb * 3 + 1] - py) * k1
                 + (xyz[nb * 3 + 2] - pz) * k2;
        float v = xp[nb * CCH + c] + pe;
        m = fmaxf(m, v);
    }
    h[n * CCH + c] = h[n * CCH + c] + (m * g[c] * RSQ + b[c]);
}

// ---------------- split-fp16 tensor-core GEMM (3-term, ldmatrix, pre-split B) --------------
// C(R x M) = epilogue( prologue(A)(R x K) @ B(K x M) )
// BM=64, BN=128, BK=16, 256 threads (8 warps, 2x4), warp tile 32x32.
// A: fp16 hi/lo split in-kernel at load; B: pre-split fp16 hi/lo pulled via cp.async.

#define BM 64
#define BN 128
#define BK 16

__device__ __forceinline__ unsigned su32(const void* p) {
    return (unsigned)__cvta_generic_to_shared(p);
}

__device__ __forceinline__ void cpasync16(unsigned smem, const void* gmem) {
    asm volatile("cp.async.cg.shared.global [%0], [%1], 16;" :: "r"(smem), "l"(gmem));
}

__device__ __forceinline__ void ldsm4(unsigned& r0, unsigned& r1, unsigned& r2,
                                      unsigned& r3, unsigned addr) {
    asm volatile("ldmatrix.sync.aligned.m8n8.x4.shared.b16 {%0,%1,%2,%3}, [%4];"
                 : "=r"(r0), "=r"(r1), "=r"(r2), "=r"(r3) : "r"(addr));
}

__device__ __forceinline__ void mma16(float* c, const unsigned* a, const unsigned* b) {
    asm volatile(
        "mma.sync.aligned.m16n8k16.row.col.f32.f16.f16.f32 "
        "{%0,%1,%2,%3}, {%4,%5,%6,%7}, {%8,%9}, {%0,%1,%2,%3};"
        : "+f"(c[0]), "+f"(c[1]), "+f"(c[2]), "+f"(c[3])
        : "r"(a[0]), "r"(a[1]), "r"(a[2]), "r"(a[3]), "r"(b[0]), "r"(b[1]));
}

// split a,b into fp16 hi pair + fp16 lo pair (a in low half)
__device__ __forceinline__ void split2h(float a, float b, unsigned& hi, unsigned& lo) {
    __half ha = __float2half_rn(a);
    __half hb = __float2half_rn(b);
    __half la = __float2half_rn(a - __half2float(ha));
    __half lb = __float2half_rn(b - __half2float(hb));
    __half2 H = __halves2half2(ha, hb);
    __half2 L = __halves2half2(la, lb);
    hi = *reinterpret_cast<unsigned*>(&H);
    lo = *reinterpret_cast<unsigned*>(&L);
}

__global__ void __launch_bounds__(256) gemm_tc(
    const float* __restrict__ A,
    const __half* __restrict__ Bhi, const __half* __restrict__ Blo,
    float* Cout, int K, int M,
    const float* __restrict__ a_scale, const float* __restrict__ a_bias,
    const float* __restrict__ bias, int act,
    const float* __restrict__ bn_g, const float* __restrict__ bn_b,
    const float* residual)
{
    __shared__ __align__(16) __half sAh[2][2][BM][8];
    __shared__ __align__(16) __half sAl[2][2][BM][8];
    __shared__ __align__(16) __half sBh[2][2][BN][8];
    __shared__ __align__(16) __half sBl[2][2][BN][8];

    int t = threadIdx.x;
    int lane = t & 31, wid = t >> 5;
    int wm = wid >> 2;      // 0..1  -> rows wm*32
    int wn = wid & 3;       // 0..3  -> cols wn*32
    int bm = blockIdx.x * BM;
    int bn = blockIdx.y * BN;
    int gid = lane >> 2;    // groupID 0..7
    int tig = lane & 3;     // thread-in-group 0..3

    // ---- ldmatrix per-lane addresses ----
    int a_lm  = (lane & 7) + ((lane >> 3) & 1) * 8;
    int a_lkh = (lane >> 4) & 1;
    unsigned aAdH[2], aAdL[2];
    #pragma unroll
    for (int mt = 0; mt < 2; ++mt) {
        int m = wm * 32 + mt * 16 + a_lm;
        aAdH[mt] = su32(&sAh[0][a_lkh][m][0]);
        aAdL[mt] = su32(&sAl[0][a_lkh][m][0]);
    }
    int b_ln  = (lane & 7) + ((lane >> 4) & 1) * 8;
    int b_lkh = (lane >> 3) & 1;
    unsigned bAdH[2], bAdL[2];
    #pragma unroll
    for (int ntp = 0; ntp < 2; ++ntp) {
        int n = wn * 32 + ntp * 16 + b_ln;
        bAdH[ntp] = su32(&sBh[0][b_lkh][n][0]);
        bAdL[ntp] = su32(&sBl[0][b_lkh][n][0]);
    }
    const unsigned ABUF = 2 * BM * 8 * 2;   // bytes per A buffer (2048)
    const unsigned BBUF = 2 * BN * 8 * 2;   // bytes per B buffer (4096)

    // ---- global load mappings ----
    int a_row = t >> 2;
    int a_k4  = (t & 3) << 2;
    int a_kh  = a_k4 >> 3;
    int a_kc  = a_k4 & 7;
    int b_n  = t & 127;
    int b_kh = t >> 7;
    // B pre-split element offset for iteration it: ((it*2 + b_kh)*M + bn + b_n)*8
    size_t b_base = ((size_t)b_kh * M + bn + b_n) << 3;
    size_t b_step = ((size_t)2 * M) << 3;
    unsigned sbh = su32(&sBh[0][b_kh][b_n][0]);
    unsigned sbl = su32(&sBl[0][b_kh][b_n][0]);

    float acc[2][4][4] = {};
    int niter = K / BK;

    // ---- preload buffer 0 ----
    {
        float4 av = *(const float4*)&A[(size_t)(bm + a_row) * K + a_k4];
        if (a_scale) {
            av.x = av.x * a_scale[a_k4 + 0] * RSQ + a_bias[a_k4 + 0];
            av.y = av.y * a_scale[a_k4 + 1] * RSQ + a_bias[a_k4 + 1];
            av.z = av.z * a_scale[a_k4 + 2] * RSQ + a_bias[a_k4 + 2];
            av.w = av.w * a_scale[a_k4 + 3] * RSQ + a_bias[a_k4 + 3];
        }
        unsigned h0, l0, h1, l1;
        split2h(av.x, av.y, h0, l0);
        split2h(av.z, av.w, h1, l1);
        *(uint2*)&sAh[0][a_kh][a_row][a_kc] = make_uint2(h0, h1);
        *(uint2*)&sAl[0][a_kh][a_row][a_kc] = make_uint2(l0, l1);

        cpasync16(sbh, Bhi + b_base);
        cpasync16(sbl, Blo + b_base);
        asm volatile("cp.async.commit_group;");
        asm volatile("cp.async.wait_group 0;");
    }
    __syncthreads();

    for (int it = 0; it < niter; ++it) {
        int cur = it & 1;
        bool more = (it + 1 < niter);
        int nxt = cur ^ 1;

        float4 av;
        if (more) {
            // B: async copy into next buffer (overlaps with MMA below)
            size_t off = b_base + (size_t)(it + 1) * b_step;
            cpasync16(sbh + nxt * BBUF, Bhi + off);
            cpasync16(sbl + nxt * BBUF, Blo + off);
            asm volatile("cp.async.commit_group;");
            // A: prefetch + transform in registers
            int k0 = (it + 1) * BK;
            av = *(const float4*)&A[(size_t)(bm + a_row) * K + k0 + a_k4];
            if (a_scale) {
                av.x = av.x * a_scale[k0 + a_k4 + 0] * RSQ + a_bias[k0 + a_k4 + 0];
                av.y = av.y * a_scale[k0 + a_k4 + 1] * RSQ + a_bias[k0 + a_k4 + 1];
                av.z = av.z * a_scale[k0 + a_k4 + 2] * RSQ + a_bias[k0 + a_k4 + 2];
                av.w = av.w * a_scale[k0 + a_k4 + 3] * RSQ + a_bias[k0 + a_k4 + 3];
            }
        }

        // fragments via ldmatrix
        unsigned ah[2][4], al[2][4], bh[4][2], bl[4][2];
        #pragma unroll
        for (int mt = 0; mt < 2; ++mt) {
            ldsm4(ah[mt][0], ah[mt][1], ah[mt][2], ah[mt][3], aAdH[mt] + cur * ABUF);
            ldsm4(al[mt][0], al[mt][1], al[mt][2], al[mt][3], aAdL[mt] + cur * ABUF);
        }
        #pragma unroll
        for (int ntp = 0; ntp < 2; ++ntp) {
            unsigned r0, r1, r2, r3;
            ldsm4(r0, r1, r2, r3, bAdH[ntp] + cur * BBUF);
            bh[ntp * 2][0] = r0; bh[ntp * 2][1] = r1;
            bh[ntp * 2 + 1][0] = r2; bh[ntp * 2 + 1][1] = r3;
            ldsm4(r0, r1, r2, r3, bAdL[ntp] + cur * BBUF);
            bl[ntp * 2][0] = r0; bl[ntp * 2][1] = r1;
            bl[ntp * 2 + 1][0] = r2; bl[ntp * 2 + 1][1] = r3;
        }

        #pragma unroll
        for (int mt = 0; mt < 2; ++mt)
            #pragma unroll
            for (int nt = 0; nt < 4; ++nt) {
                mma16(acc[mt][nt], al[mt], bh[nt]);
                mma16(acc[mt][nt], ah[mt], bl[nt]);
                mma16(acc[mt][nt], ah[mt], bh[nt]);
            }

        if (more) {
            unsigned h0, l0, h1, l1;
            split2h(av.x, av.y, h0, l0);
            split2h(av.z, av.w, h1, l1);
            *(uint2*)&sAh[nxt][a_kh][a_row][a_kc] = make_uint2(h0, h1);
            *(uint2*)&sAl[nxt][a_kh][a_row][a_kc] = make_uint2(l0, l1);
            asm volatile("cp.async.wait_group 0;");
            __syncthreads();
        }
    }

    // --- epilogue ---
    #pragma unroll
    for (int mt = 0; mt < 2; ++mt) {
        #pragma unroll
        for (int nt = 0; nt < 4; ++nt) {
            int c0 = bn + wn * 32 + nt * 8 + tig * 2;
            #pragma unroll
            for (int half = 0; half < 2; ++half) {
                int row = bm + wm * 32 + mt * 16 + gid + half * 8;
                float v0 = acc[mt][nt][half * 2 + 0];
                float v1 = acc[mt][nt][half * 2 + 1];
                if (bias) { v0 += bias[c0]; v1 += bias[c0 + 1]; }
                if (act)  { v0 = gelu_tanh(v0); v1 = gelu_tanh(v1); }
                if (bn_g) {
                    v0 = v0 * bn_g[c0] * RSQ + bn_b[c0];
                    v1 = v1 * bn_g[c0 + 1] * RSQ + bn_b[c0 + 1];
                }
                size_t idx = (size_t)row * M + c0;
                if (residual) { v0 += residual[idx]; v1 += residual[idx + 1]; }
                *(float2*)&Cout[idx] = make_float2(v0, v1);
            }
        }
    }
}

// ---------------- driver ----------------
extern "C" void kernel_launch(void* const* d_in, const int* in_sizes, int n_in,
                              void* d_out, int out_size)
{
    const float* x      = (const float*)d_in[0];
    const float* xyz    = (const float*)d_in[1];
    const int*   knn    = (const int*)  d_in[2];
    const float* spse_m = (const float*)d_in[3];
    const float* spse_c = (const float*)d_in[4];
    const float* spse_h = (const float*)d_in[5];
    const float* bn0g   = (const float*)d_in[6];
    const float* bn0b   = (const float*)d_in[7];
    const float* w1     = (const float*)d_in[8];
    const float* b1     = (const float*)d_in[9];
    const float* w2     = (const float*)d_in[10];
    const float* bng    = (const float*)d_in[11];
    const float* bnb    = (const float*)d_in[12];
    const float* proj   = (const float*)d_in[13];
    const float* coor   = (const float*)d_in[14];
    const float* scl    = (const float*)d_in[15];
    const float* lbng   = (const float*)d_in[16];
    const float* lbnb   = (const float*)d_in[17];
    const float* mw1    = (const float*)d_in[18];
    const float* mb1    = (const float*)d_in[19];
    const float* mw2    = (const float*)d_in[20];
    const float* mbng   = (const float*)d_in[21];
    const float* mbnb   = (const float*)d_in[22];
    const float* pg     = (const float*)d_in[23];
    const float* pb     = (const float*)d_in[24];
    const float* pw     = (const float*)d_in[25];
    float* out = (float*)d_out;

    float *h, *xp, *tmp;
    __half *whi, *wlo;
    cudaGetSymbolAddress((void**)&h,   g_h);
    cudaGetSymbolAddress((void**)&xp,  g_xp);
    cudaGetSymbolAddress((void**)&tmp, g_tmp);
    cudaGetSymbolAddress((void**)&whi, g_whi);
    cudaGetSymbolAddress((void**)&wlo, g_wlo);

    dim3 blk(256);
    dim3 gM128(625, 1), gM256(625, 2), gM512(625, 4);

    // pre-split all weights (runs every launch; deterministic)
    wsplit_all<<<(WTOT + 255) / 256, 256>>>(w1, w2, mw1, mw2, proj, pw);
    // nbr = bn0(knn_spse4(...))
    spse_kernel<<<NPTS, 128>>>(x, xyz, knn, spse_m, spse_c, spse_h, bn0g, bn0b, xp);
    // h = bn( gelu(nbr @ w1 + b1) @ w2 )
    gemm_tc<<<gM256, blk>>>(xp, whi + OFF_W1, wlo + OFF_W1, tmp, 128, 256,
                            0, 0, b1, 1, 0, 0, 0);
    gemm_tc<<<gM128, blk>>>(tmp, whi + OFF_W2, wlo + OFF_W2, h, 256, 128,
                            0, 0, 0, 0, bng, bnb, 0);
    // h += mlp0(h)
    gemm_tc<<<gM512, blk>>>(h, whi + OFF_MW1, wlo + OFF_MW1, tmp, 128, 512,
                            0, 0, mb1, 1, 0, 0, 0);
    gemm_tc<<<gM128, blk>>>(tmp, whi + OFF_MW2, wlo + OFF_MW2, h, 512, 128,
                            0, 0, 0, 0, mbng, mbnb, h);

    for (int i = 0; i < 4; ++i) {
        gemm_tc<<<gM128, blk>>>(h, whi + OFF_PROJ + i * 16384, wlo + OFF_PROJ + i * 16384,
                                xp, 128, 128, 0, 0, 0, 0, 0, 0, 0);
        lfp_kernel<<<NPTS, 128>>>(xp, xyz, knn, coor + i * 3 * 32, scl + i * 32,
                                  lbng + i * CCH, lbnb + i * CCH, h);
        if (i & 1) {
            int j = i / 2 + 1;
            gemm_tc<<<gM512, blk>>>(h, whi + OFF_MW1 + j * 65536, wlo + OFF_MW1 + j * 65536,
                                    tmp, 128, 512, 0, 0, mb1 + j * 512, 1, 0, 0, 0);
            gemm_tc<<<gM128, blk>>>(tmp, whi + OFF_MW2 + j * 65536, wlo + OFF_MW2 + j * 65536,
                                    h, 512, 128, 0, 0, 0, 0, mbng + j * CCH, mbnb + j * CCH, h);
        }
    }
    // out = bn(h) @ post_w   (BN folded into A prologue)
    gemm_tc<<<gM256, blk>>>(h, whi + OFF_PW, wlo + OFF_PW, out, 128, 256,
                            pg, pb, 0, 0, 0, 0, 0);
}

// round 9
// speedup vs baseline: 1.5621x; 1.0310x over previous
#include <cuda_runtime.h>
#include <cuda_fp16.h>
#include <math.h>

#define NPTS 40000
#define KNN  16
#define CCH  128
// 1/sqrt(1 + 1e-5)  (BatchNorm eval with running_var = 1)
#define RSQ  0.9999950000374997f

// ---------------- scratch (no allocations allowed) ----------------
static __device__ float g_h  [NPTS * CCH];   // main residual stream (f32)
static __device__ float g_xp [NPTS * CCH];   // lfp proj output (f32)

// pre-split activations (fp16 hi/lo), tiled [plane = kt*2+kh][row][8]
static __device__ __half g_hhi[NPTS * CCH],  g_hlo[NPTS * CCH];   // K=128 stream
static __device__ __half g_thi[NPTS * 512],  g_tlo[NPTS * 512];   // MLP hidden

// pre-split weights (fp16 hi/lo), tiled [kt][kh][n][8]
#define OFF_W1   0         // (128,256)
#define OFF_W2   32768     // (256,128)
#define OFF_MW1  65536     // 3 x (128,512)
#define OFF_MW2  262144    // 3 x (512,128)
#define OFF_PROJ 458752    // 4 x (128,128)
#define OFF_PW   524288    // (128,256)
#define WTOT     557056
static __device__ __half g_whi[WTOT];
static __device__ __half g_wlo[WTOT];

__device__ __forceinline__ float gelu_tanh(float x) {
    float x3 = x * x * x;
    return 0.5f * x * (1.0f + tanhf(0.7978845608028654f * (x + 0.044715f * x3)));
}

// split-layout destination index for (row, channel c) with row-count NPTS
__device__ __forceinline__ size_t split_idx(int row, int c) {
    return ((size_t)((c >> 4) * 2 + ((c >> 3) & 1)) * NPTS + row) * 8 + (c & 7);
}

// ---------------- weight pre-split ----------------
__device__ __forceinline__ void wsplit_one(const float* __restrict__ W, int lidx,
                                           int M, int base) {
    int k = lidx / M, n = lidx - k * M;
    int kt = k >> 4, kh = (k >> 3) & 1, j = k & 7;
    float v = W[lidx];
    __half h = __float2half_rn(v);
    int dst = base + (((kt * 2 + kh) * M + n) << 3) + j;
    g_whi[dst] = h;
    g_wlo[dst] = __float2half_rn(v - __half2float(h));
}

__global__ void __launch_bounds__(256) wsplit_all(
    const float* __restrict__ w1, const float* __restrict__ w2,
    const float* __restrict__ mw1, const float* __restrict__ mw2,
    const float* __restrict__ proj, const float* __restrict__ pw)
{
    int idx = blockIdx.x * 256 + threadIdx.x;
    if (idx < 32768) wsplit_one(w1, idx, 256, OFF_W1);
    else if (idx < 65536) wsplit_one(w2, idx - 32768, 128, OFF_W2);
    else if (idx < 262144) {
        int l = idx - 65536; int j = l >> 16;
        wsplit_one(mw1 + (j << 16), l & 65535, 512, OFF_MW1 + (j << 16));
    } else if (idx < 458752) {
        int l = idx - 262144; int j = l >> 16;
        wsplit_one(mw2 + (j << 16), l & 65535, 128, OFF_MW2 + (j << 16));
    } else if (idx < 524288) {
        int l = idx - 458752; int i = l >> 14;
        wsplit_one(proj + (i << 14), l & 16383, 128, OFF_PROJ + (i << 14));
    } else if (idx < WTOT) wsplit_one(pw, idx - 524288, 256, OFF_PW);
}

// ---------------- spse + BN0 -> split output ----------------
__global__ void __launch_bounds__(128) spse_kernel(
    const float* __restrict__ x, const float* __restrict__ xyz,
    const int* __restrict__ knn,
    const float* __restrict__ spse_m, const float* __restrict__ spse_c,
    const float* __restrict__ spse_h,
    const float* __restrict__ g0, const float* __restrict__ b0,
    __half* __restrict__ ohi, __half* __restrict__ olo)
{
    int n = blockIdx.x;
    int c = threadIdx.x;

    float M0x = spse_m[0 * CCH + c], M0y = spse_m[1 * CCH + c], M0z = spse_m[2 * CCH + c];
    float M1x = spse_m[4 * CCH + c], M1y = spse_m[5 * CCH + c], M1z = spse_m[6 * CCH + c];
    float M2x = spse_m[8 * CCH + c], M2y = spse_m[9 * CCH + c], M2z = spse_m[10 * CCH + c];
    float c0 = spse_c[0 * CCH + c]; c0 *= c0;
    float c1 = spse_c[1 * CCH + c]; c1 *= c1;
    float c2 = spse_c[2 * CCH + c]; c2 *= c2;
    float h2 = spse_h[c]; h2 *= h2;

    float px = xyz[n * 3 + 0], py = xyz[n * 3 + 1], pz = xyz[n * 3 + 2];
    float f0 = x[n * 4 + 0], f1 = x[n * 4 + 1], f2 = x[n * 4 + 2], f3 = x[n * 4 + 3];

    float e = 0.0f;
    #pragma unroll
    for (int k = 0; k < KNN; ++k) {
        int nb = knn[n * KNN + k];
        float dx = xyz[nb * 3 + 0] - px;
        float dy = xyz[nb * 3 + 1] - py;
        float dz = xyz[nb * 3 + 2] - pz;
        float r0 = x[nb * 4 + 0] - f0;
        float r1 = x[nb * 4 + 1] - f1;
        float r2 = x[nb * 4 + 2] - f2;
        float r3 = x[nb * 4 + 3] - f3;
        float d0 = dx * M0x + dy * M0y + dz * M0z;
        float d1 = dx * M1x + dy * M1y + dz * M1z;
        float d2 = dx * M2x + dy * M2y + dz * M2z;
        e += d0 * d0 + d1 * d1 + d2 * d2;
        e += r0 * r0 * c0 + r1 * r1 * c1 + r2 * r2 * c2 + r3 * r3 * h2;
    }
    float r = sqrtf(e * (1.0f / (float)KNN));
    float v = r * g0[c] * RSQ + b0[c];
    size_t d = split_idx(n, c);
    __half hh = __float2half_rn(v);
    ohi[d] = hh;
    olo[d] = __float2half_rn(v - __half2float(hh));
}

// ---------------- LFP gather + PE + max + BN + residual (+ split h) ----------------
__global__ void __launch_bounds__(128) lfp_kernel(
    const float* __restrict__ xp, const float* __restrict__ xyz,
    const int* __restrict__ knn,
    const float* __restrict__ coor,  // (3, 32)
    const float* __restrict__ scale, // (32,)
    const float* __restrict__ g, const float* __restrict__ b,
    float* h, __half* __restrict__ ohi, __half* __restrict__ olo)
{
    int n = blockIdx.x;
    int c = threadIdx.x;
    int d = c >> 2;
    float s2 = scale[d]; s2 *= s2;
    float k0 = coor[0 * 32 + d] * s2;
    float k1 = coor[1 * 32 + d] * s2;
    float k2 = coor[2 * 32 + d] * s2;

    float px = xyz[n * 3 + 0], py = xyz[n * 3 + 1], pz = xyz[n * 3 + 2];

    float m = -INFINITY;
    #pragma unroll
    for (int k = 0; k < KNN; ++k) {
        int nb = knn[n * KNN + k];
        float pe = (xyz[nb * 3 + 0] - px) * k0
                 + (xyz[nb * 3 + 1] - py) * k1
                 + (xyz[nb * 3 + 2] - pz) * k2;
        float v = xp[nb * CCH + c] + pe;
        m = fmaxf(m, v);
    }
    float v = h[n * CCH + c] + (m * g[c] * RSQ + b[c]);
    h[n * CCH + c] = v;
    size_t dd = split_idx(n, c);
    __half hh = __float2half_rn(v);
    ohi[dd] = hh;
    olo[dd] = __float2half_rn(v - __half2float(hh));
}

// ---------------- split-fp16 GEMM: pre-split A & B, 3-stage cp.async pipeline -----------
// C(R x M) = epilogue( A(R x K) @ B(K x M) ),  R = NPTS.
// BM=64, BN=128, BK=16, 256 threads (8 warps, 2x4), warp tile 32x32.

#define BM 64
#define BN 128
#define BK 16
#define NSTAGE 3
#define A_STAGE_BYTES (2 * 2 * BM * 8 * 2)   // 4096
#define B_STAGE_BYTES (2 * 2 * BN * 8 * 2)   // 8192

__device__ __forceinline__ unsigned su32(const void* p) {
    return (unsigned)__cvta_generic_to_shared(p);
}
__device__ __forceinline__ void cpasync16(unsigned smem, const void* gmem) {
    asm volatile("cp.async.cg.shared.global [%0], [%1], 16;" :: "r"(smem), "l"(gmem));
}
__device__ __forceinline__ void ldsm4(unsigned& r0, unsigned& r1, unsigned& r2,
                                      unsigned& r3, unsigned addr) {
    asm volatile("ldmatrix.sync.aligned.m8n8.x4.shared.b16 {%0,%1,%2,%3}, [%4];"
                 : "=r"(r0), "=r"(r1), "=r"(r2), "=r"(r3) : "r"(addr));
}
__device__ __forceinline__ void mma16(float* c, const unsigned* a, const unsigned* b) {
    asm volatile(
        "mma.sync.aligned.m16n8k16.row.col.f32.f16.f16.f32 "
        "{%0,%1,%2,%3}, {%4,%5,%6,%7}, {%8,%9}, {%0,%1,%2,%3};"
        : "+f"(c[0]), "+f"(c[1]), "+f"(c[2]), "+f"(c[3])
        : "r"(a[0]), "r"(a[1]), "r"(a[2]), "r"(a[3]), "r"(b[0]), "r"(b[1]));
}

__global__ void __launch_bounds__(256) gemm_tc(
    const __half* __restrict__ Ahi, const __half* __restrict__ Alo,
    const __half* __restrict__ Bhi, const __half* __restrict__ Blo,
    float* Cf32, int K, int M,
    const float* __restrict__ bias, int act,
    const float* __restrict__ bn_g, const float* __restrict__ bn_b,
    const float* residual,
    __half* Ohi, __half* Olo,
    const float* __restrict__ og, const float* __restrict__ ob)
{
    // [stage][hl][kh][row][8]
    __shared__ __align__(16) __half sA[NSTAGE][2][2][BM][8];   // 12 KB
    __shared__ __align__(16) __half sB[NSTAGE][2][2][BN][8];   // 24 KB

    int t = threadIdx.x;
    int lane = t & 31, wid = t >> 5;
    int wm = wid >> 2;
    int wn = wid & 3;
    int bm = blockIdx.x * BM;
    int bn = blockIdx.y * BN;
    int gid = lane >> 2;
    int tig = lane & 3;

    // ---- fill mappings ----
    int fa_hl = t >> 7;             // 0..1
    int fa_kh = (t >> 6) & 1;
    int fa_m  = t & 63;
    const __half* fa_src = fa_hl ? Alo : Ahi;
    unsigned fa_dst = su32(&sA[0][fa_hl][fa_kh][fa_m][0]);

    const __half* fb_src[2];
    unsigned fb_dst[2];
    size_t fb_off[2];
    #pragma unroll
    for (int s = 0; s < 2; ++s) {
        int v = t + 256 * s;
        int hl = v >> 8, r = v & 255, kh = r >> 7, n = r & 127;
        fb_src[s] = hl ? Blo : Bhi;
        fb_dst[s] = su32(&sB[0][hl][kh][n][0]);
        fb_off[s] = ((size_t)kh * M + bn + n) * 8;
    }
    size_t fa_off = ((size_t)fa_kh * NPTS + bm + fa_m) * 8;
    size_t a_step = (size_t)2 * NPTS * 8;   // per kt
    size_t b_step = (size_t)2 * M * 8;

    // ---- ldmatrix per-lane addresses (buffer 0) ----
    int a_lm  = (lane & 7) + ((lane >> 3) & 1) * 8;
    int a_lkh = (lane >> 4) & 1;
    unsigned aAdH[2], aAdL[2];
    #pragma unroll
    for (int mt = 0; mt < 2; ++mt) {
        int m = wm * 32 + mt * 16 + a_lm;
        aAdH[mt] = su32(&sA[0][0][a_lkh][m][0]);
        aAdL[mt] = su32(&sA[0][1][a_lkh][m][0]);
    }
    int b_ln  = (lane & 7) + ((lane >> 4) & 1) * 8;
    int b_lkh = (lane >> 3) & 1;
    unsigned bAdH[2], bAdL[2];
    #pragma unroll
    for (int ntp = 0; ntp < 2; ++ntp) {
        int n = wn * 32 + ntp * 16 + b_ln;
        bAdH[ntp] = su32(&sB[0][0][b_lkh][n][0]);
        bAdL[ntp] = su32(&sB[0][1][b_lkh][n][0]);
    }

    float acc[2][4][4] = {};
    int niter = K / BK;

    // ---- prologue: issue stages 0,1 ----
    #pragma unroll
    for (int p = 0; p < 2; ++p) {
        if (p < niter) {
            cpasync16(fa_dst + p * A_STAGE_BYTES, fa_src + fa_off + (size_t)p * a_step);
            #pragma unroll
            for (int s = 0; s < 2; ++s)
                cpasync16(fb_dst[s] + p * B_STAGE_BYTES,
                          fb_src[s] + fb_off[s] + (size_t)p * b_step);
        }
        asm volatile("cp.async.commit_group;");
    }

    for (int it = 0; it < niter; ++it) {
        int kt = it + 2;
        if (kt < niter) {
            int buf = kt % NSTAGE;
            cpasync16(fa_dst + buf * A_STAGE_BYTES, fa_src + fa_off + (size_t)kt * a_step);
            #pragma unroll
            for (int s = 0; s < 2; ++s)
                cpasync16(fb_dst[s] + buf * B_STAGE_BYTES,
                          fb_src[s] + fb_off[s] + (size_t)kt * b_step);
        }
        asm volatile("cp.async.commit_group;");
        asm volatile("cp.async.wait_group %0;" :: "n"(NSTAGE - 1));
        __syncthreads();

        int cur = it % NSTAGE;
        unsigned ah[2][4], al[2][4], bh[4][2], bl[4][2];
        #pragma unroll
        for (int mt = 0; mt < 2; ++mt) {
            ldsm4(ah[mt][0], ah[mt][1], ah[mt][2], ah[mt][3], aAdH[mt] + cur * A_STAGE_BYTES);
            ldsm4(al[mt][0], al[mt][1], al[mt][2], al[mt][3], aAdL[mt] + cur * A_STAGE_BYTES);
        }
        #pragma unroll
        for (int ntp = 0; ntp < 2; ++ntp) {
            unsigned r0, r1, r2, r3;
            ldsm4(r0, r1, r2, r3, bAdH[ntp] + cur * B_STAGE_BYTES);
            bh[ntp * 2][0] = r0; bh[ntp * 2][1] = r1;
            bh[ntp * 2 + 1][0] = r2; bh[ntp * 2 + 1][1] = r3;
            ldsm4(r0, r1, r2, r3, bAdL[ntp] + cur * B_STAGE_BYTES);
            bl[ntp * 2][0] = r0; bl[ntp * 2][1] = r1;
            bl[ntp * 2 + 1][0] = r2; bl[ntp * 2 + 1][1] = r3;
        }

        #pragma unroll
        for (int mt = 0; mt < 2; ++mt)
            #pragma unroll
            for (int nt = 0; nt < 4; ++nt) {
                mma16(acc[mt][nt], al[mt], bh[nt]);
                mma16(acc[mt][nt], ah[mt], bl[nt]);
                mma16(acc[mt][nt], ah[mt], bh[nt]);
            }
        __syncthreads();
    }

    // --- epilogue ---
    #pragma unroll
    for (int mt = 0; mt < 2; ++mt) {
        #pragma unroll
        for (int nt = 0; nt < 4; ++nt) {
            int c0 = bn + wn * 32 + nt * 8 + tig * 2;
            #pragma unroll
            for (int half = 0; half < 2; ++half) {
                int row = bm + wm * 32 + mt * 16 + gid + half * 8;
                float v0 = acc[mt][nt][half * 2 + 0];
                float v1 = acc[mt][nt][half * 2 + 1];
                if (bias) { v0 += bias[c0]; v1 += bias[c0 + 1]; }
                if (act)  { v0 = gelu_tanh(v0); v1 = gelu_tanh(v1); }
                if (bn_g) {
                    v0 = v0 * bn_g[c0] * RSQ + bn_b[c0];
                    v1 = v1 * bn_g[c0 + 1] * RSQ + bn_b[c0 + 1];
                }
                size_t idx = (size_t)row * M + c0;
                if (residual) { v0 += residual[idx]; v1 += residual[idx + 1]; }
                if (Cf32) *(float2*)&Cf32[idx] = make_float2(v0, v1);
                if (Ohi) {
                    float s0 = v0, s1 = v1;
                    if (og) {
                        s0 = s0 * og[c0] * RSQ + ob[c0];
                        s1 = s1 * og[c0 + 1] * RSQ + ob[c0 + 1];
                    }
                    __half h0 = __float2half_rn(s0);
                    __half h1 = __float2half_rn(s1);
                    __half l0 = __float2half_rn(s0 - __half2float(h0));
                    __half l1 = __float2half_rn(s1 - __half2float(h1));
                    size_t od = split_idx(row, c0);
                    *(__half2*)&Ohi[od] = __halves2half2(h0, h1);
                    *(__half2*)&Olo[od] = __halves2half2(l0, l1);
                }
            }
        }
    }
}

// ---------------- driver ----------------
extern "C" void kernel_launch(void* const* d_in, const int* in_sizes, int n_in,
                              void* d_out, int out_size)
{
    const float* x      = (const float*)d_in[0];
    const float* xyz    = (const float*)d_in[1];
    const int*   knn    = (const int*)  d_in[2];
    const float* spse_m = (const float*)d_in[3];
    const float* spse_c = (const float*)d_in[4];
    const float* spse_h = (const float*)d_in[5];
    const float* bn0g   = (const float*)d_in[6];
    const float* bn0b   = (const float*)d_in[7];
    const float* w1     = (const float*)d_in[8];
    const float* b1     = (const float*)d_in[9];
    const float* w2     = (const float*)d_in[10];
    const float* bng    = (const float*)d_in[11];
    const float* bnb    = (const float*)d_in[12];
    const float* proj   = (const float*)d_in[13];
    const float* coor   = (const float*)d_in[14];
    const float* scl    = (const float*)d_in[15];
    const float* lbng   = (const float*)d_in[16];
    const float* lbnb   = (const float*)d_in[17];
    const float* mw1    = (const float*)d_in[18];
    const float* mb1    = (const float*)d_in[19];
    const float* mw2    = (const float*)d_in[20];
    const float* mbng   = (const float*)d_in[21];
    const float* mbnb   = (const float*)d_in[22];
    const float* pg     = (const float*)d_in[23];
    const float* pb     = (const float*)d_in[24];
    const float* pw     = (const float*)d_in[25];
    float* out = (float*)d_out;

    float *h, *xp;
    __half *whi, *wlo, *hhi, *hlo, *thi, *tlo;
    cudaGetSymbolAddress((void**)&h,   g_h);
    cudaGetSymbolAddress((void**)&xp,  g_xp);
    cudaGetSymbolAddress((void**)&whi, g_whi);
    cudaGetSymbolAddress((void**)&wlo, g_wlo);
    cudaGetSymbolAddress((void**)&hhi, g_hhi);
    cudaGetSymbolAddress((void**)&hlo, g_hlo);
    cudaGetSymbolAddress((void**)&thi, g_thi);
    cudaGetSymbolAddress((void**)&tlo, g_tlo);

    dim3 blk(256);
    dim3 gM128(625, 1), gM256(625, 2), gM512(625, 4);

    // pre-split all weights
    wsplit_all<<<(WTOT + 255) / 256, 256>>>(w1, w2, mw1, mw2, proj, pw);
    // nbr = bn0(knn_spse4(...)) -> split
    spse_kernel<<<NPTS, 128>>>(x, xyz, knn, spse_m, spse_c, spse_h, bn0g, bn0b, hhi, hlo);
    // tmp = gelu(nbr @ w1 + b1)         (split only)
    gemm_tc<<<gM256, blk>>>(hhi, hlo, whi + OFF_W1, wlo + OFF_W1, 0, 128, 256,
                            b1, 1, 0, 0, 0, thi, tlo, 0, 0);
    // h = bn(tmp @ w2)                  (f32 + split)
    gemm_tc<<<gM128, blk>>>(thi, tlo, whi + OFF_W2, wlo + OFF_W2, h, 256, 128,
                            0, 0, bng, bnb, 0, hhi, hlo, 0, 0);
    // tmp = gelu(h @ mw1_0 + mb1_0)
    gemm_tc<<<gM512, blk>>>(hhi, hlo, whi + OFF_MW1, wlo + OFF_MW1, 0, 128, 512,
                            mb1, 1, 0, 0, 0, thi, tlo, 0, 0);
    // h += bn(tmp @ mw2_0)
    gemm_tc<<<gM128, blk>>>(thi, tlo, whi + OFF_MW2, wlo + OFF_MW2, h, 512, 128,
                            0, 0, mbng, mbnb, h, hhi, hlo, 0, 0);

    for (int i = 0; i < 4; ++i) {
        // xp = h @ proj[i]  (f32 only; lfp gathers f32)
        gemm_tc<<<gM128, blk>>>(hhi, hlo, whi + OFF_PROJ + i * 16384,
                                wlo + OFF_PROJ + i * 16384, xp, 128, 128,
                                0, 0, 0, 0, 0, 0, 0, 0, 0);
        // h += bn(max_k(xp[knn] + pe))   (f32 + split)
        lfp_kernel<<<NPTS, 128>>>(xp, xyz, knn, coor + i * 3 * 32, scl + i * 32,
                                  lbng + i * CCH, lbnb + i * CCH, h, hhi, hlo);
        if (i & 1) {
            int j = i / 2 + 1;
            bool last = (j == 2);
            gemm_tc<<<gM512, blk>>>(hhi, hlo, whi + OFF_MW1 + j * 65536,
                                    wlo + OFF_MW1 + j * 65536, 0, 128, 512,
                                    mb1 + j * 512, 1, 0, 0, 0, thi, tlo, 0, 0);
            // h += bn(tmp @ mw2_j); last one also folds post-BN into the split copy
            gemm_tc<<<gM128, blk>>>(thi, tlo, whi + OFF_MW2 + j * 65536,
                                    wlo + OFF_MW2 + j * 65536,
                                    last ? 0 : h, 512, 128,
                                    0, 0, mbng + j * CCH, mbnb + j * CCH, h,
                                    hhi, hlo, last ? pg : 0, last ? pb : 0);
        }
    }
    // out = bn(h) @ post_w  (BN already folded into the split h)
    gemm_tc<<<gM256, blk>>>(hhi, hlo, whi + OFF_PW, wlo + OFF_PW, out, 128, 256,
                            0, 0, 0, 0, 0, 0, 0, 0, 0);
}

// round 10
// speedup vs baseline: 1.8030x; 1.1542x over previous
#include <cuda_runtime.h>
#include <cuda_fp16.h>
#include <math.h>

#define NPTS 40000
#define KNN  16
#define CCH  128
// 1/sqrt(1 + 1e-5)  (BatchNorm eval with running_var = 1)
#define RSQ  0.9999950000374997f

// ---------------- scratch (no allocations allowed) ----------------
static __device__ float g_h  [NPTS * CCH];   // main residual stream (f32)
static __device__ float g_xp [NPTS * CCH];   // lfp proj output (f32)

// pre-split activations (fp16 hi/lo), tiled [plane = kt*2+kh][row][8]
static __device__ __half g_hhi[NPTS * CCH],  g_hlo[NPTS * CCH];   // K=128 stream
static __device__ __half g_thi[NPTS * 512],  g_tlo[NPTS * 512];   // MLP hidden

// pre-split weights (fp16 hi/lo), tiled [kt][kh][n][8]
#define OFF_W1   0         // (128,256)
#define OFF_W2   32768     // (256,128)
#define OFF_MW1  65536     // 3 x (128,512)
#define OFF_MW2  262144    // 3 x (512,128)
#define OFF_PROJ 458752    // 4 x (128,128)
#define OFF_PW   524288    // (128,256)
#define WTOT     557056
static __device__ __half g_whi[WTOT];
static __device__ __half g_wlo[WTOT];

__device__ __forceinline__ float gelu_tanh(float x) {
    float x3 = x * x * x;
    return 0.5f * x * (1.0f + tanhf(0.7978845608028654f * (x + 0.044715f * x3)));
}

// split-layout destination index for (row, channel c) with row-count NPTS
__device__ __forceinline__ size_t split_idx(int row, int c) {
    return ((size_t)((c >> 4) * 2 + ((c >> 3) & 1)) * NPTS + row) * 8 + (c & 7);
}

// ---------------- weight pre-split ----------------
__device__ __forceinline__ void wsplit_one(const float* __restrict__ W, int lidx,
                                           int M, int base) {
    int k = lidx / M, n = lidx - k * M;
    int kt = k >> 4, kh = (k >> 3) & 1, j = k & 7;
    float v = W[lidx];
    __half h = __float2half_rn(v);
    int dst = base + (((kt * 2 + kh) * M + n) << 3) + j;
    g_whi[dst] = h;
    g_wlo[dst] = __float2half_rn(v - __half2float(h));
}

__global__ void __launch_bounds__(256) wsplit_all(
    const float* __restrict__ w1, const float* __restrict__ w2,
    const float* __restrict__ mw1, const float* __restrict__ mw2,
    const float* __restrict__ proj, const float* __restrict__ pw)
{
    int idx = blockIdx.x * 256 + threadIdx.x;
    if (idx < 32768) wsplit_one(w1, idx, 256, OFF_W1);
    else if (idx < 65536) wsplit_one(w2, idx - 32768, 128, OFF_W2);
    else if (idx < 262144) {
        int l = idx - 65536; int j = l >> 16;
        wsplit_one(mw1 + (j << 16), l & 65535, 512, OFF_MW1 + (j << 16));
    } else if (idx < 458752) {
        int l = idx - 262144; int j = l >> 16;
        wsplit_one(mw2 + (j << 16), l & 65535, 128, OFF_MW2 + (j << 16));
    } else if (idx < 524288) {
        int l = idx - 458752; int i = l >> 14;
        wsplit_one(proj + (i << 14), l & 16383, 128, OFF_PROJ + (i << 14));
    } else if (idx < WTOT) wsplit_one(pw, idx - 524288, 256, OFF_PW);
}

// ---------------- spse + BN0 -> split output ----------------
__global__ void __launch_bounds__(128) spse_kernel(
    const float* __restrict__ x, const float* __restrict__ xyz,
    const int* __restrict__ knn,
    const float* __restrict__ spse_m, const float* __restrict__ spse_c,
    const float* __restrict__ spse_h,
    const float* __restrict__ g0, const float* __restrict__ b0,
    __half* __restrict__ ohi, __half* __restrict__ olo)
{
    int n = blockIdx.x;
    int c = threadIdx.x;
    int lane = c & 31;

    float M0x = spse_m[0 * CCH + c], M0y = spse_m[1 * CCH + c], M0z = spse_m[2 * CCH + c];
    float M1x = spse_m[4 * CCH + c], M1y = spse_m[5 * CCH + c], M1z = spse_m[6 * CCH + c];
    float M2x = spse_m[8 * CCH + c], M2y = spse_m[9 * CCH + c], M2z = spse_m[10 * CCH + c];
    float c0 = spse_c[0 * CCH + c]; c0 *= c0;
    float c1 = spse_c[1 * CCH + c]; c1 *= c1;
    float c2 = spse_c[2 * CCH + c]; c2 *= c2;
    float h2 = spse_h[c]; h2 *= h2;

    float px = xyz[n * 3 + 0], py = xyz[n * 3 + 1], pz = xyz[n * 3 + 2];
    float f0 = x[n * 4 + 0], f1 = x[n * 4 + 1], f2 = x[n * 4 + 2], f3 = x[n * 4 + 3];

    // all 16 neighbor indices fetched in one shot per warp, broadcast via shfl
    int myidx = (lane < KNN) ? knn[n * KNN + lane] : 0;

    float e = 0.0f;
    #pragma unroll
    for (int k = 0; k < KNN; ++k) {
        int nb = __shfl_sync(0xffffffffu, myidx, k);
        float dx = xyz[nb * 3 + 0] - px;
        float dy = xyz[nb * 3 + 1] - py;
        float dz = xyz[nb * 3 + 2] - pz;
        float4 xv = *(const float4*)&x[nb * 4];
        float r0 = xv.x - f0;
        float r1 = xv.y - f1;
        float r2 = xv.z - f2;
        float r3 = xv.w - f3;
        float d0 = dx * M0x + dy * M0y + dz * M0z;
        float d1 = dx * M1x + dy * M1y + dz * M1z;
        float d2 = dx * M2x + dy * M2y + dz * M2z;
        e += d0 * d0 + d1 * d1 + d2 * d2;
        e += r0 * r0 * c0 + r1 * r1 * c1 + r2 * r2 * c2 + r3 * r3 * h2;
    }
    float r = sqrtf(e * (1.0f / (float)KNN));
    float v = r * g0[c] * RSQ + b0[c];
    size_t d = split_idx(n, c);
    __half hh = __float2half_rn(v);
    ohi[d] = hh;
    olo[d] = __float2half_rn(v - __half2float(hh));
}

// ---------------- LFP: warp-per-point, float4, gather + PE + max + BN + residual -------
// 256 threads = 8 warps = 8 points per block; lane owns 4 channels (c = lane*4..+3),
// which share one PE channel d = lane.
__global__ void __launch_bounds__(256) lfp_kernel(
    const float* __restrict__ xp, const float* __restrict__ xyz,
    const int* __restrict__ knn,
    const float* __restrict__ coor,  // (3, 32)
    const float* __restrict__ scale, // (32,)
    const float* __restrict__ g, const float* __restrict__ b,
    float* h, __half* __restrict__ ohi, __half* __restrict__ olo)
{
    int warp = threadIdx.x >> 5;
    int lane = threadIdx.x & 31;
    int n = blockIdx.x * 8 + warp;           // 5000 * 8 = 40000 exactly

    float s2 = scale[lane]; s2 *= s2;
    float k0 = coor[0 * 32 + lane] * s2;
    float k1 = coor[1 * 32 + lane] * s2;
    float k2 = coor[2 * 32 + lane] * s2;

    float px = xyz[n * 3 + 0], py = xyz[n * 3 + 1], pz = xyz[n * 3 + 2];

    int myidx = (lane < KNN) ? knn[n * KNN + lane] : 0;

    float4 m = make_float4(-INFINITY, -INFINITY, -INFINITY, -INFINITY);
    #pragma unroll
    for (int k = 0; k < KNN; ++k) {
        int nb = __shfl_sync(0xffffffffu, myidx, k);
        float pe = (xyz[nb * 3 + 0] - px) * k0
                 + (xyz[nb * 3 + 1] - py) * k1
                 + (xyz[nb * 3 + 2] - pz) * k2;
        float4 v = *(const float4*)&xp[(size_t)nb * CCH + lane * 4];
        m.x = fmaxf(m.x, v.x + pe);
        m.y = fmaxf(m.y, v.y + pe);
        m.z = fmaxf(m.z, v.z + pe);
        m.w = fmaxf(m.w, v.w + pe);
    }

    int c = lane * 4;
    float4 gv = *(const float4*)&g[c];
    float4 bv = *(const float4*)&b[c];
    float4 hv = *(const float4*)&h[(size_t)n * CCH + c];
    float4 o;
    o.x = hv.x + (m.x * gv.x * RSQ + bv.x);
    o.y = hv.y + (m.y * gv.y * RSQ + bv.y);
    o.z = hv.z + (m.z * gv.z * RSQ + bv.z);
    o.w = hv.w + (m.w * gv.w * RSQ + bv.w);
    *(float4*)&h[(size_t)n * CCH + c] = o;

    // split store: c&7 in {0,4} -> 4 consecutive halves, 8B aligned
    size_t od = split_idx(n, c);
    __half h0 = __float2half_rn(o.x), h1 = __float2half_rn(o.y);
    __half h2_ = __float2half_rn(o.z), h3 = __float2half_rn(o.w);
    __half2 hi01 = __halves2half2(h0, h1);
    __half2 hi23 = __halves2half2(h2_, h3);
    __half2 lo01 = __halves2half2(__float2half_rn(o.x - __half2float(h0)),
                                  __float2half_rn(o.y - __half2float(h1)));
    __half2 lo23 = __halves2half2(__float2half_rn(o.z - __half2float(h2_)),
                                  __float2half_rn(o.w - __half2float(h3)));
    *(__half2*)&ohi[od]     = hi01;
    *(__half2*)&ohi[od + 2] = hi23;
    *(__half2*)&olo[od]     = lo01;
    *(__half2*)&olo[od + 2] = lo23;
}

// ---------------- split-fp16 GEMM: pre-split A & B, 3-stage cp.async pipeline -----------
// C(R x M) = epilogue( A(R x K) @ B(K x M) ),  R = NPTS.
// BM=64, BN=128, BK=16, 256 threads (8 warps, 2x4), warp tile 32x32.

#define BM 64
#define BN 128
#define BK 16
#define NSTAGE 3
#define A_STAGE_BYTES (2 * 2 * BM * 8 * 2)   // 4096
#define B_STAGE_BYTES (2 * 2 * BN * 8 * 2)   // 8192

__device__ __forceinline__ unsigned su32(const void* p) {
    return (unsigned)__cvta_generic_to_shared(p);
}
__device__ __forceinline__ void cpasync16(unsigned smem, const void* gmem) {
    asm volatile("cp.async.cg.shared.global [%0], [%1], 16;" :: "r"(smem), "l"(gmem));
}
__device__ __forceinline__ void ldsm4(unsigned& r0, unsigned& r1, unsigned& r2,
                                      unsigned& r3, unsigned addr) {
    asm volatile("ldmatrix.sync.aligned.m8n8.x4.shared.b16 {%0,%1,%2,%3}, [%4];"
                 : "=r"(r0), "=r"(r1), "=r"(r2), "=r"(r3) : "r"(addr));
}
__device__ __forceinline__ void mma16(float* c, const unsigned* a, const unsigned* b) {
    asm volatile(
        "mma.sync.aligned.m16n8k16.row.col.f32.f16.f16.f32 "
        "{%0,%1,%2,%3}, {%4,%5,%6,%7}, {%8,%9}, {%0,%1,%2,%3};"
        : "+f"(c[0]), "+f"(c[1]), "+f"(c[2]), "+f"(c[3])
        : "r"(a[0]), "r"(a[1]), "r"(a[2]), "r"(a[3]), "r"(b[0]), "r"(b[1]));
}

__global__ void __launch_bounds__(256) gemm_tc(
    const __half* __restrict__ Ahi, const __half* __restrict__ Alo,
    const __half* __restrict__ Bhi, const __half* __restrict__ Blo,
    float* Cf32, int K, int M,
    const float* __restrict__ bias, int act,
    const float* __restrict__ bn_g, const float* __restrict__ bn_b,
    const float* residual,
    __half* Ohi, __half* Olo,
    const float* __restrict__ og, const float* __restrict__ ob)
{
    // [stage][hl][kh][row][8]
    __shared__ __align__(16) __half sA[NSTAGE][2][2][BM][8];   // 12 KB
    __shared__ __align__(16) __half sB[NSTAGE][2][2][BN][8];   // 24 KB

    int t = threadIdx.x;
    int lane = t & 31, wid = t >> 5;
    int wm = wid >> 2;
    int wn = wid & 3;
    int bm = blockIdx.x * BM;
    int bn = blockIdx.y * BN;
    int gid = lane >> 2;
    int tig = lane & 3;

    // ---- fill mappings ----
    int fa_hl = t >> 7;             // 0..1
    int fa_kh = (t >> 6) & 1;
    int fa_m  = t & 63;
    const __half* fa_src = fa_hl ? Alo : Ahi;
    unsigned fa_dst = su32(&sA[0][fa_hl][fa_kh][fa_m][0]);

    const __half* fb_src[2];
    unsigned fb_dst[2];
    size_t fb_off[2];
    #pragma unroll
    for (int s = 0; s < 2; ++s) {
        int v = t + 256 * s;
        int hl = v >> 8, r = v & 255, kh = r >> 7, n = r & 127;
        fb_src[s] = hl ? Blo : Bhi;
        fb_dst[s] = su32(&sB[0][hl][kh][n][0]);
        fb_off[s] = ((size_t)kh * M + bn + n) * 8;
    }
    size_t fa_off = ((size_t)fa_kh * NPTS + bm + fa_m) * 8;
    size_t a_step = (size_t)2 * NPTS * 8;   // per kt
    size_t b_step = (size_t)2 * M * 8;

    // ---- ldmatrix per-lane addresses (buffer 0) ----
    int a_lm  = (lane & 7) + ((lane >> 3) & 1) * 8;
    int a_lkh = (lane >> 4) & 1;
    unsigned aAdH[2], aAdL[2];
    #pragma unroll
    for (int mt = 0; mt < 2; ++mt) {
        int m = wm * 32 + mt * 16 + a_lm;
        aAdH[mt] = su32(&sA[0][0][a_lkh][m][0]);
        aAdL[mt] = su32(&sA[0][1][a_lkh][m][0]);
    }
    int b_ln  = (lane & 7) + ((lane >> 4) & 1) * 8;
    int b_lkh = (lane >> 3) & 1;
    unsigned bAdH[2], bAdL[2];
    #pragma unroll
    for (int ntp = 0; ntp < 2; ++ntp) {
        int n = wn * 32 + ntp * 16 + b_ln;
        bAdH[ntp] = su32(&sB[0][0][b_lkh][n][0]);
        bAdL[ntp] = su32(&sB[0][1][b_lkh][n][0]);
    }

    float acc[2][4][4] = {};
    int niter = K / BK;

    // ---- prologue: issue stages 0,1 ----
    #pragma unroll
    for (int p = 0; p < 2; ++p) {
        if (p < niter) {
            cpasync16(fa_dst + p * A_STAGE_BYTES, fa_src + fa_off + (size_t)p * a_step);
            #pragma unroll
            for (int s = 0; s < 2; ++s)
                cpasync16(fb_dst[s] + p * B_STAGE_BYTES,
                          fb_src[s] + fb_off[s] + (size_t)p * b_step);
        }
        asm volatile("cp.async.commit_group;");
    }

    for (int it = 0; it < niter; ++it) {
        int kt = it + 2;
        if (kt < niter) {
            int buf = kt % NSTAGE;
            cpasync16(fa_dst + buf * A_STAGE_BYTES, fa_src + fa_off + (size_t)kt * a_step);
            #pragma unroll
            for (int s = 0; s < 2; ++s)
                cpasync16(fb_dst[s] + buf * B_STAGE_BYTES,
                          fb_src[s] + fb_off[s] + (size_t)kt * b_step);
        }
        asm volatile("cp.async.commit_group;");
        asm volatile("cp.async.wait_group %0;" :: "n"(NSTAGE - 1));
        __syncthreads();

        int cur = it % NSTAGE;
        unsigned ah[2][4], al[2][4], bh[4][2], bl[4][2];
        #pragma unroll
        for (int mt = 0; mt < 2; ++mt) {
            ldsm4(ah[mt][0], ah[mt][1], ah[mt][2], ah[mt][3], aAdH[mt] + cur * A_STAGE_BYTES);
            ldsm4(al[mt][0], al[mt][1], al[mt][2], al[mt][3], aAdL[mt] + cur * A_STAGE_BYTES);
        }
        #pragma unroll
        for (int ntp = 0; ntp < 2; ++ntp) {
            unsigned r0, r1, r2, r3;
            ldsm4(r0, r1, r2, r3, bAdH[ntp] + cur * B_STAGE_BYTES);
            bh[ntp * 2][0] = r0; bh[ntp * 2][1] = r1;
            bh[ntp * 2 + 1][0] = r2; bh[ntp * 2 + 1][1] = r3;
            ldsm4(r0, r1, r2, r3, bAdL[ntp] + cur * B_STAGE_BYTES);
            bl[ntp * 2][0] = r0; bl[ntp * 2][1] = r1;
            bl[ntp * 2 + 1][0] = r2; bl[ntp * 2 + 1][1] = r3;
        }

        #pragma unroll
        for (int mt = 0; mt < 2; ++mt)
            #pragma unroll
            for (int nt = 0; nt < 4; ++nt) {
                mma16(acc[mt][nt], al[mt], bh[nt]);
                mma16(acc[mt][nt], ah[mt], bl[nt]);
                mma16(acc[mt][nt], ah[mt], bh[nt]);
            }
        __syncthreads();
    }

    // --- epilogue ---
    #pragma unroll
    for (int mt = 0; mt < 2; ++mt) {
        #pragma unroll
        for (int nt = 0; nt < 4; ++nt) {
            int c0 = bn + wn * 32 + nt * 8 + tig * 2;
            #pragma unroll
            for (int half = 0; half < 2; ++half) {
                int row = bm + wm * 32 + mt * 16 + gid + half * 8;
                float v0 = acc[mt][nt][half * 2 + 0];
                float v1 = acc[mt][nt][half * 2 + 1];
                if (bias) { v0 += bias[c0]; v1 += bias[c0 + 1]; }
                if (act)  { v0 = gelu_tanh(v0); v1 = gelu_tanh(v1); }
                if (bn_g) {
                    v0 = v0 * bn_g[c0] * RSQ + bn_b[c0];
                    v1 = v1 * bn_g[c0 + 1] * RSQ + bn_b[c0 + 1];
                }
                size_t idx = (size_t)row * M + c0;
                if (residual) { v0 += residual[idx]; v1 += residual[idx + 1]; }
                if (Cf32) *(float2*)&Cf32[idx] = make_float2(v0, v1);
                if (Ohi) {
                    float s0 = v0, s1 = v1;
                    if (og) {
                        s0 = s0 * og[c0] * RSQ + ob[c0];
                        s1 = s1 * og[c0 + 1] * RSQ + ob[c0 + 1];
                    }
                    __half h0 = __float2half_rn(s0);
                    __half h1 = __float2half_rn(s1);
                    __half l0 = __float2half_rn(s0 - __half2float(h0));
                    __half l1 = __float2half_rn(s1 - __half2float(h1));
                    size_t od = split_idx(row, c0);
                    *(__half2*)&Ohi[od] = __halves2half2(h0, h1);
                    *(__half2*)&Olo[od] = __halves2half2(l0, l1);
                }
            }
        }
    }
}

// ---------------- driver ----------------
extern "C" void kernel_launch(void* const* d_in, const int* in_sizes, int n_in,
                              void* d_out, int out_size)
{
    const float* x      = (const float*)d_in[0];
    const float* xyz    = (const float*)d_in[1];
    const int*   knn    = (const int*)  d_in[2];
    const float* spse_m = (const float*)d_in[3];
    const float* spse_c = (const float*)d_in[4];
    const float* spse_h = (const float*)d_in[5];
    const float* bn0g   = (const float*)d_in[6];
    const float* bn0b   = (const float*)d_in[7];
    const float* w1     = (const float*)d_in[8];
    const float* b1     = (const float*)d_in[9];
    const float* w2     = (const float*)d_in[10];
    const float* bng    = (const float*)d_in[11];
    const float* bnb    = (const float*)d_in[12];
    const float* proj   = (const float*)d_in[13];
    const float* coor   = (const float*)d_in[14];
    const float* scl    = (const float*)d_in[15];
    const float* lbng   = (const float*)d_in[16];
    const float* lbnb   = (const float*)d_in[17];
    const float* mw1    = (const float*)d_in[18];
    const float* mb1    = (const float*)d_in[19];
    const float* mw2    = (const float*)d_in[20];
    const float* mbng   = (const float*)d_in[21];
    const float* mbnb   = (const float*)d_in[22];
    const float* pg     = (const float*)d_in[23];
    const float* pb     = (const float*)d_in[24];
    const float* pw     = (const float*)d_in[25];
    float* out = (float*)d_out;

    float *h, *xp;
    __half *whi, *wlo, *hhi, *hlo, *thi, *tlo;
    cudaGetSymbolAddress((void**)&h,   g_h);
    cudaGetSymbolAddress((void**)&xp,  g_xp);
    cudaGetSymbolAddress((void**)&whi, g_whi);
    cudaGetSymbolAddress((void**)&wlo, g_wlo);
    cudaGetSymbolAddress((void**)&hhi, g_hhi);
    cudaGetSymbolAddress((void**)&hlo, g_hlo);
    cudaGetSymbolAddress((void**)&thi, g_thi);
    cudaGetSymbolAddress((void**)&tlo, g_tlo);

    dim3 blk(256);
    dim3 gM128(625, 1), gM256(625, 2), gM512(625, 4);

    // pre-split all weights
    wsplit_all<<<(WTOT + 255) / 256, 256>>>(w1, w2, mw1, mw2, proj, pw);
    // nbr = bn0(knn_spse4(...)) -> split
    spse_kernel<<<NPTS, 128>>>(x, xyz, knn, spse_m, spse_c, spse_h, bn0g, bn0b, hhi, hlo);
    // tmp = gelu(nbr @ w1 + b1)         (split only)
    gemm_tc<<<gM256, blk>>>(hhi, hlo, whi + OFF_W1, wlo + OFF_W1, 0, 128, 256,
                            b1, 1, 0, 0, 0, thi, tlo, 0, 0);
    // h = bn(tmp @ w2)                  (f32 + split)
    gemm_tc<<<gM128, blk>>>(thi, tlo, whi + OFF_W2, wlo + OFF_W2, h, 256, 128,
                            0, 0, bng, bnb, 0, hhi, hlo, 0, 0);
    // tmp = gelu(h @ mw1_0 + mb1_0)
    gemm_tc<<<gM512, blk>>>(hhi, hlo, whi + OFF_MW1, wlo + OFF_MW1, 0, 128, 512,
                            mb1, 1, 0, 0, 0, thi, tlo, 0, 0);
    // h += bn(tmp @ mw2_0)
    gemm_tc<<<gM128, blk>>>(thi, tlo, whi + OFF_MW2, wlo + OFF_MW2, h, 512, 128,
                            0, 0, mbng, mbnb, h, hhi, hlo, 0, 0);

    for (int i = 0; i < 4; ++i) {
        // xp = h @ proj[i]  (f32 only; lfp gathers f32)
        gemm_tc<<<gM128, blk>>>(hhi, hlo, whi + OFF_PROJ + i * 16384,
                                wlo + OFF_PROJ + i * 16384, xp, 128, 128,
                                0, 0, 0, 0, 0, 0, 0, 0, 0);
        // h += bn(max_k(xp[knn] + pe))   (f32 + split)
        lfp_kernel<<<NPTS / 8, 256>>>(xp, xyz, knn, coor + i * 3 * 32, scl + i * 32,
                                      lbng + i * CCH, lbnb + i * CCH, h, hhi, hlo);
        if (i & 1) {
            int j = i / 2 + 1;
            bool last = (j == 2);
            gemm_tc<<<gM512, blk>>>(hhi, hlo, whi + OFF_MW1 + j * 65536,
                                    wlo + OFF_MW1 + j * 65536, 0, 128, 512,
                                    mb1 + j * 512, 1, 0, 0, 0, thi, tlo, 0, 0);
            // h += bn(tmp @ mw2_j); last one also folds post-BN into the split copy
            gemm_tc<<<gM128, blk>>>(thi, tlo, whi + OFF_MW2 + j * 65536,
                                    wlo + OFF_MW2 + j * 65536,
                                    last ? 0 : h, 512, 128,
                                    0, 0, mbng + j * CCH, mbnb + j * CCH, h,
                                    hhi, hlo, last ? pg : 0, last ? pb : 0);
        }
    }
    // out = bn(h) @ post_w  (BN already folded into the split h)
    gemm_tc<<<gM256, blk>>>(hhi, hlo, whi + OFF_PW, wlo + OFF_PW, out, 128, 256,
                            0, 0, 0, 0, 0, 0, 0, 0, 0);
}

// round 11
// speedup vs baseline: 1.9064x; 1.0574x over previous
#include <cuda_runtime.h>
#include <cuda_fp16.h>
#include <math.h>

#define NPTS 40000
#define KNN  16
#define CCH  128
// 1/sqrt(1 + 1e-5)  (BatchNorm eval with running_var = 1)
#define RSQ  0.9999950000374997f

// ---------------- scratch (no allocations allowed) ----------------
static __device__ float g_h  [NPTS * CCH];   // main residual stream (f32)
static __device__ float g_xp [NPTS * CCH];   // lfp proj output (f32)
static __device__ float4 g_pk[NPTS * 2];     // packed per-point: [2n]=(xyz,0), [2n+1]=feat

// pre-split activations (fp16 hi/lo), tiled [plane = kt*2+kh][row][8]
static __device__ __half g_hhi[NPTS * CCH],  g_hlo[NPTS * CCH];   // K=128 stream
static __device__ __half g_thi[NPTS * 512],  g_tlo[NPTS * 512];   // MLP hidden

// pre-split weights (fp16 hi/lo), tiled [kt][kh][n][8]
#define OFF_W1   0         // (128,256)
#define OFF_W2   32768     // (256,128)
#define OFF_MW1  65536     // 3 x (128,512)
#define OFF_MW2  262144    // 3 x (512,128)
#define OFF_PROJ 458752    // 4 x (128,128)
#define OFF_PW   524288    // (128,256)
#define WTOT     557056
static __device__ __half g_whi[WTOT];
static __device__ __half g_wlo[WTOT];

__device__ __forceinline__ float gelu_tanh(float x) {
    float x3 = x * x * x;
    return 0.5f * x * (1.0f + tanhf(0.7978845608028654f * (x + 0.044715f * x3)));
}

// split-layout destination index for (row, channel c) with row-count NPTS
__device__ __forceinline__ size_t split_idx(int row, int c) {
    return ((size_t)((c >> 4) * 2 + ((c >> 3) & 1)) * NPTS + row) * 8 + (c & 7);
}

// ---------------- pack xyz + feat into 32B records ----------------
__global__ void __launch_bounds__(256) pack_kernel(
    const float* __restrict__ xyz, const float* __restrict__ x,
    float4* __restrict__ pk)
{
    int n = blockIdx.x * 256 + threadIdx.x;
    if (n >= NPTS) return;
    pk[2 * n]     = make_float4(xyz[n * 3 + 0], xyz[n * 3 + 1], xyz[n * 3 + 2], 0.0f);
    pk[2 * n + 1] = *(const float4*)&x[n * 4];
}

// ---------------- weight pre-split ----------------
__device__ __forceinline__ void wsplit_one(const float* __restrict__ W, int lidx,
                                           int M, int base) {
    int k = lidx / M, n = lidx - k * M;
    int kt = k >> 4, kh = (k >> 3) & 1, j = k & 7;
    float v = W[lidx];
    __half h = __float2half_rn(v);
    int dst = base + (((kt * 2 + kh) * M + n) << 3) + j;
    g_whi[dst] = h;
    g_wlo[dst] = __float2half_rn(v - __half2float(h));
}

__global__ void __launch_bounds__(256) wsplit_all(
    const float* __restrict__ w1, const float* __restrict__ w2,
    const float* __restrict__ mw1, const float* __restrict__ mw2,
    const float* __restrict__ proj, const float* __restrict__ pw)
{
    int idx = blockIdx.x * 256 + threadIdx.x;
    if (idx < 32768) wsplit_one(w1, idx, 256, OFF_W1);
    else if (idx < 65536) wsplit_one(w2, idx - 32768, 128, OFF_W2);
    else if (idx < 262144) {
        int l = idx - 65536; int j = l >> 16;
        wsplit_one(mw1 + (j << 16), l & 65535, 512, OFF_MW1 + (j << 16));
    } else if (idx < 458752) {
        int l = idx - 262144; int j = l >> 16;
        wsplit_one(mw2 + (j << 16), l & 65535, 128, OFF_MW2 + (j << 16));
    } else if (idx < 524288) {
        int l = idx - 458752; int i = l >> 14;
        wsplit_one(proj + (i << 14), l & 16383, 128, OFF_PROJ + (i << 14));
    } else if (idx < WTOT) wsplit_one(pw, idx - 524288, 256, OFF_PW);
}

// ---------------- spse + BN0 -> split output ----------------
__global__ void __launch_bounds__(128) spse_kernel(
    const float4* __restrict__ pk,
    const int* __restrict__ knn,
    const float* __restrict__ spse_m, const float* __restrict__ spse_c,
    const float* __restrict__ spse_h,
    const float* __restrict__ g0, const float* __restrict__ b0,
    __half* __restrict__ ohi, __half* __restrict__ olo)
{
    int n = blockIdx.x;
    int c = threadIdx.x;
    int lane = c & 31;

    float M0x = spse_m[0 * CCH + c], M0y = spse_m[1 * CCH + c], M0z = spse_m[2 * CCH + c];
    float M1x = spse_m[4 * CCH + c], M1y = spse_m[5 * CCH + c], M1z = spse_m[6 * CCH + c];
    float M2x = spse_m[8 * CCH + c], M2y = spse_m[9 * CCH + c], M2z = spse_m[10 * CCH + c];
    float c0 = spse_c[0 * CCH + c]; c0 *= c0;
    float c1 = spse_c[1 * CCH + c]; c1 *= c1;
    float c2 = spse_c[2 * CCH + c]; c2 *= c2;
    float h2 = spse_h[c]; h2 *= h2;

    float4 pc = pk[2 * n];
    float4 fc = pk[2 * n + 1];

    // all 16 neighbor indices fetched in one shot per warp, broadcast via shfl
    int myidx = (lane < KNN) ? knn[n * KNN + lane] : 0;

    float e = 0.0f;
    #pragma unroll
    for (int k = 0; k < KNN; ++k) {
        int nb = __shfl_sync(0xffffffffu, myidx, k);
        float4 pn = pk[2 * nb];
        float4 fn = pk[2 * nb + 1];
        float dx = pn.x - pc.x;
        float dy = pn.y - pc.y;
        float dz = pn.z - pc.z;
        float r0 = fn.x - fc.x;
        float r1 = fn.y - fc.y;
        float r2 = fn.z - fc.z;
        float r3 = fn.w - fc.w;
        float d0 = dx * M0x + dy * M0y + dz * M0z;
        float d1 = dx * M1x + dy * M1y + dz * M1z;
        float d2 = dx * M2x + dy * M2y + dz * M2z;
        e += d0 * d0 + d1 * d1 + d2 * d2;
        e += r0 * r0 * c0 + r1 * r1 * c1 + r2 * r2 * c2 + r3 * r3 * h2;
    }
    float r = sqrtf(e * (1.0f / (float)KNN));
    float v = r * g0[c] * RSQ + b0[c];
    size_t d = split_idx(n, c);
    __half hh = __float2half_rn(v);
    ohi[d] = hh;
    olo[d] = __float2half_rn(v - __half2float(hh));
}

// ---------------- LFP: warp-per-point, float4, gather + PE + max + BN + residual -------
__global__ void __launch_bounds__(256) lfp_kernel(
    const float* __restrict__ xp, const float4* __restrict__ pk,
    const int* __restrict__ knn,
    const float* __restrict__ coor,  // (3, 32)
    const float* __restrict__ scale, // (32,)
    const float* __restrict__ g, const float* __restrict__ b,
    float* h, __half* __restrict__ ohi, __half* __restrict__ olo)
{
    int warp = threadIdx.x >> 5;
    int lane = threadIdx.x & 31;
    int n = blockIdx.x * 8 + warp;           // 5000 * 8 = 40000 exactly

    float s2 = scale[lane]; s2 *= s2;
    float k0 = coor[0 * 32 + lane] * s2;
    float k1 = coor[1 * 32 + lane] * s2;
    float k2 = coor[2 * 32 + lane] * s2;

    float4 pc = pk[2 * n];

    int myidx = (lane < KNN) ? knn[n * KNN + lane] : 0;

    float4 m = make_float4(-INFINITY, -INFINITY, -INFINITY, -INFINITY);
    #pragma unroll
    for (int k = 0; k < KNN; ++k) {
        int nb = __shfl_sync(0xffffffffu, myidx, k);
        float4 pn = pk[2 * nb];
        float pe = (pn.x - pc.x) * k0 + (pn.y - pc.y) * k1 + (pn.z - pc.z) * k2;
        float4 v = *(const float4*)&xp[(size_t)nb * CCH + lane * 4];
        m.x = fmaxf(m.x, v.x + pe);
        m.y = fmaxf(m.y, v.y + pe);
        m.z = fmaxf(m.z, v.z + pe);
        m.w = fmaxf(m.w, v.w + pe);
    }

    int c = lane * 4;
    float4 gv = *(const float4*)&g[c];
    float4 bv = *(const float4*)&b[c];
    float4 hv = *(const float4*)&h[(size_t)n * CCH + c];
    float4 o;
    o.x = hv.x + (m.x * gv.x * RSQ + bv.x);
    o.y = hv.y + (m.y * gv.y * RSQ + bv.y);
    o.z = hv.z + (m.z * gv.z * RSQ + bv.z);
    o.w = hv.w + (m.w * gv.w * RSQ + bv.w);
    *(float4*)&h[(size_t)n * CCH + c] = o;

    // split store: c&7 in {0,4} -> 4 consecutive halves, 8B aligned
    size_t od = split_idx(n, c);
    __half h0 = __float2half_rn(o.x), h1 = __float2half_rn(o.y);
    __half h2_ = __float2half_rn(o.z), h3 = __float2half_rn(o.w);
    *(__half2*)&ohi[od]     = __halves2half2(h0, h1);
    *(__half2*)&ohi[od + 2] = __halves2half2(h2_, h3);
    *(__half2*)&olo[od]     = __halves2half2(__float2half_rn(o.x - __half2float(h0)),
                                             __float2half_rn(o.y - __half2float(h1)));
    *(__half2*)&olo[od + 2] = __halves2half2(__float2half_rn(o.z - __half2float(h2_)),
                                             __float2half_rn(o.w - __half2float(h3)));
}

// ---------------- split-fp16 GEMM: pre-split A & B, 3-stage cp.async pipeline -----------
// C(R x M) = epilogue( A(R x K) @ B(K x M) ),  R = NPTS.
// BM=64, BN=128, BK=16, 256 threads (8 warps, 2x4), warp tile 32x32.
// __launch_bounds__(256, 3): clamp regs to ~85 -> 3 blocks/SM residency.

#define BM 64
#define BN 128
#define BK 16
#define NSTAGE 3
#define A_STAGE_BYTES (2 * 2 * BM * 8 * 2)   // 4096
#define B_STAGE_BYTES (2 * 2 * BN * 8 * 2)   // 8192

__device__ __forceinline__ unsigned su32(const void* p) {
    return (unsigned)__cvta_generic_to_shared(p);
}
__device__ __forceinline__ void cpasync16(unsigned smem, const void* gmem) {
    asm volatile("cp.async.cg.shared.global [%0], [%1], 16;" :: "r"(smem), "l"(gmem));
}
__device__ __forceinline__ void ldsm4(unsigned& r0, unsigned& r1, unsigned& r2,
                                      unsigned& r3, unsigned addr) {
    asm volatile("ldmatrix.sync.aligned.m8n8.x4.shared.b16 {%0,%1,%2,%3}, [%4];"
                 : "=r"(r0), "=r"(r1), "=r"(r2), "=r"(r3) : "r"(addr));
}
__device__ __forceinline__ void mma16(float* c, const unsigned* a, const unsigned* b) {
    asm volatile(
        "mma.sync.aligned.m16n8k16.row.col.f32.f16.f16.f32 "
        "{%0,%1,%2,%3}, {%4,%5,%6,%7}, {%8,%9}, {%0,%1,%2,%3};"
        : "+f"(c[0]), "+f"(c[1]), "+f"(c[2]), "+f"(c[3])
        : "r"(a[0]), "r"(a[1]), "r"(a[2]), "r"(a[3]), "r"(b[0]), "r"(b[1]));
}

__global__ void __launch_bounds__(256, 3) gemm_tc(
    const __half* __restrict__ Ahi, const __half* __restrict__ Alo,
    const __half* __restrict__ Bhi, const __half* __restrict__ Blo,
    float* Cf32, int K, int M,
    const float* __restrict__ bias, int act,
    const float* __restrict__ bn_g, const float* __restrict__ bn_b,
    const float* residual,
    __half* Ohi, __half* Olo,
    const float* __restrict__ og, const float* __restrict__ ob)
{
    // [stage][hl][kh][row][8]
    __shared__ __align__(16) __half sA[NSTAGE][2][2][BM][8];   // 12 KB
    __shared__ __align__(16) __half sB[NSTAGE][2][2][BN][8];   // 24 KB

    int t = threadIdx.x;
    int lane = t & 31, wid = t >> 5;
    int wm = wid >> 2;
    int wn = wid & 3;
    int bm = blockIdx.x * BM;
    int bn = blockIdx.y * BN;
    int gid = lane >> 2;
    int tig = lane & 3;

    // ---- fill mappings ----
    int fa_hl = t >> 7;             // 0..1
    int fa_kh = (t >> 6) & 1;
    int fa_m  = t & 63;
    const __half* fa_src = fa_hl ? Alo : Ahi;
    unsigned fa_dst = su32(&sA[0][fa_hl][fa_kh][fa_m][0]);

    const __half* fb_src[2];
    unsigned fb_dst[2];
    size_t fb_off[2];
    #pragma unroll
    for (int s = 0; s < 2; ++s) {
        int v = t + 256 * s;
        int hl = v >> 8, r = v & 255, kh = r >> 7, n = r & 127;
        fb_src[s] = hl ? Blo : Bhi;
        fb_dst[s] = su32(&sB[0][hl][kh][n][0]);
        fb_off[s] = ((size_t)kh * M + bn + n) * 8;
    }
    size_t fa_off = ((size_t)fa_kh * NPTS + bm + fa_m) * 8;
    size_t a_step = (size_t)2 * NPTS * 8;   // per kt
    size_t b_step = (size_t)2 * M * 8;

    // ---- ldmatrix per-lane addresses (buffer 0) ----
    int a_lm  = (lane & 7) + ((lane >> 3) & 1) * 8;
    int a_lkh = (lane >> 4) & 1;
    unsigned aAdH[2], aAdL[2];
    #pragma unroll
    for (int mt = 0; mt < 2; ++mt) {
        int m = wm * 32 + mt * 16 + a_lm;
        aAdH[mt] = su32(&sA[0][0][a_lkh][m][0]);
        aAdL[mt] = su32(&sA[0][1][a_lkh][m][0]);
    }
    int b_ln  = (lane & 7) + ((lane >> 4) & 1) * 8;
    int b_lkh = (lane >> 3) & 1;
    unsigned bAdH[2], bAdL[2];
    #pragma unroll
    for (int ntp = 0; ntp < 2; ++ntp) {
        int n = wn * 32 + ntp * 16 + b_ln;
        bAdH[ntp] = su32(&sB[0][0][b_lkh][n][0]);
        bAdL[ntp] = su32(&sB[0][1][b_lkh][n][0]);
    }

    float acc[2][4][4] = {};
    int niter = K / BK;

    // ---- prologue: issue stages 0,1 ----
    #pragma unroll
    for (int p = 0; p < 2; ++p) {
        if (p < niter) {
            cpasync16(fa_dst + p * A_STAGE_BYTES, fa_src + fa_off + (size_t)p * a_step);
            #pragma unroll
            for (int s = 0; s < 2; ++s)
                cpasync16(fb_dst[s] + p * B_STAGE_BYTES,
                          fb_src[s] + fb_off[s] + (size_t)p * b_step);
        }
        asm volatile("cp.async.commit_group;");
    }

    for (int it = 0; it < niter; ++it) {
        int kt = it + 2;
        if (kt < niter) {
            int buf = kt % NSTAGE;
            cpasync16(fa_dst + buf * A_STAGE_BYTES, fa_src + fa_off + (size_t)kt * a_step);
            #pragma unroll
            for (int s = 0; s < 2; ++s)
                cpasync16(fb_dst[s] + buf * B_STAGE_BYTES,
                          fb_src[s] + fb_off[s] + (size_t)kt * b_step);
        }
        asm volatile("cp.async.commit_group;");
        asm volatile("cp.async.wait_group %0;" :: "n"(NSTAGE - 1));
        __syncthreads();

        int cur = it % NSTAGE;
        unsigned ah[2][4], al[2][4], bh[4][2], bl[4][2];
        #pragma unroll
        for (int mt = 0; mt < 2; ++mt) {
            ldsm4(ah[mt][0], ah[mt][1], ah[mt][2], ah[mt][3], aAdH[mt] + cur * A_STAGE_BYTES);
            ldsm4(al[mt][0], al[mt][1], al[mt][2], al[mt][3], aAdL[mt] + cur * A_STAGE_BYTES);
        }
        #pragma unroll
        for (int ntp = 0; ntp < 2; ++ntp) {
            unsigned r0, r1, r2, r3;
            ldsm4(r0, r1, r2, r3, bAdH[ntp] + cur * B_STAGE_BYTES);
            bh[ntp * 2][0] = r0; bh[ntp * 2][1] = r1;
            bh[ntp * 2 + 1][0] = r2; bh[ntp * 2 + 1][1] = r3;
            ldsm4(r0, r1, r2, r3, bAdL[ntp] + cur * B_STAGE_BYTES);
            bl[ntp * 2][0] = r0; bl[ntp * 2][1] = r1;
            bl[ntp * 2 + 1][0] = r2; bl[ntp * 2 + 1][1] = r3;
        }

        #pragma unroll
        for (int mt = 0; mt < 2; ++mt)
            #pragma unroll
            for (int nt = 0; nt < 4; ++nt) {
                mma16(acc[mt][nt], al[mt], bh[nt]);
                mma16(acc[mt][nt], ah[mt], bl[nt]);
                mma16(acc[mt][nt], ah[mt], bh[nt]);
            }
        __syncthreads();
    }

    // --- epilogue ---
    #pragma unroll
    for (int mt = 0; mt < 2; ++mt) {
        #pragma unroll
        for (int nt = 0; nt < 4; ++nt) {
            int c0 = bn + wn * 32 + nt * 8 + tig * 2;
            #pragma unroll
            for (int half = 0; half < 2; ++half) {
                int row = bm + wm * 32 + mt * 16 + gid + half * 8;
                float v0 = acc[mt][nt][half * 2 + 0];
                float v1 = acc[mt][nt][half * 2 + 1];
                if (bias) { v0 += bias[c0]; v1 += bias[c0 + 1]; }
                if (act)  { v0 = gelu_tanh(v0); v1 = gelu_tanh(v1); }
                if (bn_g) {
                    v0 = v0 * bn_g[c0] * RSQ + bn_b[c0];
                    v1 = v1 * bn_g[c0 + 1] * RSQ + bn_b[c0 + 1];
                }
                size_t idx = (size_t)row * M + c0;
                if (residual) { v0 += residual[idx]; v1 += residual[idx + 1]; }
                if (Cf32) *(float2*)&Cf32[idx] = make_float2(v0, v1);
                if (Ohi) {
                    float s0 = v0, s1 = v1;
                    if (og) {
                        s0 = s0 * og[c0] * RSQ + ob[c0];
                        s1 = s1 * og[c0 + 1] * RSQ + ob[c0 + 1];
                    }
                    __half h0 = __float2half_rn(s0);
                    __half h1 = __float2half_rn(s1);
                    __half l0 = __float2half_rn(s0 - __half2float(h0));
                    __half l1 = __float2half_rn(s1 - __half2float(h1));
                    size_t od = split_idx(row, c0);
                    *(__half2*)&Ohi[od] = __halves2half2(h0, h1);
                    *(__half2*)&Olo[od] = __halves2half2(l0, l1);
                }
            }
        }
    }
}

// ---------------- driver ----------------
extern "C" void kernel_launch(void* const* d_in, const int* in_sizes, int n_in,
                              void* d_out, int out_size)
{
    const float* x      = (const float*)d_in[0];
    const float* xyz    = (const float*)d_in[1];
    const int*   knn    = (const int*)  d_in[2];
    const float* spse_m = (const float*)d_in[3];
    const float* spse_c = (const float*)d_in[4];
    const float* spse_h = (const float*)d_in[5];
    const float* bn0g   = (const float*)d_in[6];
    const float* bn0b   = (const float*)d_in[7];
    const float* w1     = (const float*)d_in[8];
    const float* b1     = (const float*)d_in[9];
    const float* w2     = (const float*)d_in[10];
    const float* bng    = (const float*)d_in[11];
    const float* bnb    = (const float*)d_in[12];
    const float* proj   = (const float*)d_in[13];
    const float* coor   = (const float*)d_in[14];
    const float* scl    = (const float*)d_in[15];
    const float* lbng   = (const float*)d_in[16];
    const float* lbnb   = (const float*)d_in[17];
    const float* mw1    = (const float*)d_in[18];
    const float* mb1    = (const float*)d_in[19];
    const float* mw2    = (const float*)d_in[20];
    const float* mbng   = (const float*)d_in[21];
    const float* mbnb   = (const float*)d_in[22];
    const float* pg     = (const float*)d_in[23];
    const float* pb     = (const float*)d_in[24];
    const float* pw     = (const float*)d_in[25];
    float* out = (float*)d_out;

    float *h, *xp;
    float4* pk;
    __half *whi, *wlo, *hhi, *hlo, *thi, *tlo;
    cudaGetSymbolAddress((void**)&h,   g_h);
    cudaGetSymbolAddress((void**)&xp,  g_xp);
    cudaGetSymbolAddress((void**)&pk,  g_pk);
    cudaGetSymbolAddress((void**)&whi, g_whi);
    cudaGetSymbolAddress((void**)&wlo, g_wlo);
    cudaGetSymbolAddress((void**)&hhi, g_hhi);
    cudaGetSymbolAddress((void**)&hlo, g_hlo);
    cudaGetSymbolAddress((void**)&thi, g_thi);
    cudaGetSymbolAddress((void**)&tlo, g_tlo);

    dim3 blk(256);
    dim3 gM128(625, 1), gM256(625, 2), gM512(625, 4);

    // pre-split all weights + pack point records
    wsplit_all<<<(WTOT + 255) / 256, 256>>>(w1, w2, mw1, mw2, proj, pw);
    pack_kernel<<<(NPTS + 255) / 256, 256>>>(xyz, x, pk);
    // nbr = bn0(knn_spse4(...)) -> split
    spse_kernel<<<NPTS, 128>>>(pk, knn, spse_m, spse_c, spse_h, bn0g, bn0b, hhi, hlo);
    // tmp = gelu(nbr @ w1 + b1)         (split only)
    gemm_tc<<<gM256, blk>>>(hhi, hlo, whi + OFF_W1, wlo + OFF_W1, 0, 128, 256,
                            b1, 1, 0, 0, 0, thi, tlo, 0, 0);
    // h = bn(tmp @ w2)                  (f32 + split)
    gemm_tc<<<gM128, blk>>>(thi, tlo, whi + OFF_W2, wlo + OFF_W2, h, 256, 128,
                            0, 0, bng, bnb, 0, hhi, hlo, 0, 0);
    // tmp = gelu(h @ mw1_0 + mb1_0)
    gemm_tc<<<gM512, blk>>>(hhi, hlo, whi + OFF_MW1, wlo + OFF_MW1, 0, 128, 512,
                            mb1, 1, 0, 0, 0, thi, tlo, 0, 0);
    // h += bn(tmp @ mw2_0)
    gemm_tc<<<gM128, blk>>>(thi, tlo, whi + OFF_MW2, wlo + OFF_MW2, h, 512, 128,
                            0, 0, mbng, mbnb, h, hhi, hlo, 0, 0);

    for (int i = 0; i < 4; ++i) {
        // xp = h @ proj[i]  (f32 only; lfp gathers f32)
        gemm_tc<<<gM128, blk>>>(hhi, hlo, whi + OFF_PROJ + i * 16384,
                                wlo + OFF_PROJ + i * 16384, xp, 128, 128,
                                0, 0, 0, 0, 0, 0, 0, 0, 0);
        // h += bn(max_k(xp[knn] + pe))   (f32 + split)
        lfp_kernel<<<NPTS / 8, 256>>>(xp, pk, knn, coor + i * 3 * 32, scl + i * 32,
                                      lbng + i * CCH, lbnb + i * CCH, h, hhi, hlo);
        if (i & 1) {
            int j = i / 2 + 1;
            bool last = (j == 2);
            gemm_tc<<<gM512, blk>>>(hhi, hlo, whi + OFF_MW1 + j * 65536,
                                    wlo + OFF_MW1 + j * 65536, 0, 128, 512,
                                    mb1 + j * 512, 1, 0, 0, 0, thi, tlo, 0, 0);
            // h += bn(tmp @ mw2_j); last one also folds post-BN into the split copy
            gemm_tc<<<gM128, blk>>>(thi, tlo, whi + OFF_MW2 + j * 65536,
                                    wlo + OFF_MW2 + j * 65536,
                                    last ? 0 : h, 512, 128,
                                    0, 0, mbng + j * CCH, mbnb + j * CCH, h,
                                    hhi, hlo, last ? pg : 0, last ? pb : 0);
        }
    }
    // out = bn(h) @ post_w  (BN already folded into the split h)
    gemm_tc<<<gM256, blk>>>(hhi, hlo, whi + OFF_PW, wlo + OFF_PW, out, 128, 256,
                            0, 0, 0, 0, 0, 0, 0, 0, 0);
}